// round 14
// baseline (speedup 1.0000x reference)
#include <cuda_runtime.h>
#include <cuda_bf16.h>
#include <math.h>

// ---------------------------------------------------------------------------
// Problem dimensions (fixed by the reference setup)
// ---------------------------------------------------------------------------
#define B_SZ   8
#define N_PTS  500
#define M_HYP  144
#define M16    16
#define PS     8           // point slices per (b,m): 63 points each (last: 59)
#define N_ITER 9

#define C0 128
#define H0 48
#define W0 64
#define C1 64
#define H1 96
#define W1 128
#define C2 32
#define H2 192
#define W2 256

// transpose tile counts (32x32 tiles)
#define T0_TILES ((H0*W0/32) * (C0/32) * B_SZ)   // 3072
#define T1_TILES ((H1*W1/32) * (C1/32) * B_SZ)   // 6144
#define T2_TILES ((H2*W2/32) * (C2/32) * B_SZ)   // 12288

// ---------------------------------------------------------------------------
// Scratch (__device__ globals — no allocation allowed). D stored as fp32
// (round-13 profile: issue-bound, memory idle -> conversions were waste).
// ---------------------------------------------------------------------------
__device__ float g_D0[(size_t)B_SZ * H0 * W0 * C0];   // q0-r0, channel-last
__device__ float g_D1[(size_t)B_SZ * H1 * W1 * C1];
__device__ float g_D2[(size_t)B_SZ * H2 * W2 * C2];
__device__ float g_Tbuf[2][B_SZ * M_HYP * 16];       // double-buffered poses
__device__ float g_resacc[2][PS][B_SZ * M16];         // double-buffered partial residuals
__device__ float g_noise[N_ITER * B_SZ * M16 * 6];    // precomputed LM noise (m<16 only)

// ---------------------------------------------------------------------------
// Threefry-2x32 (exactly JAX's 20-round schedule; KAT-verified)
// ---------------------------------------------------------------------------
__host__ __device__ __forceinline__ void threefry2x32(
    unsigned k0, unsigned k1, unsigned x0, unsigned x1,
    unsigned* o0, unsigned* o1)
{
  unsigned ks2 = k0 ^ k1 ^ 0x1BD11BDAu;
#define TFR(r) { x0 += x1; x1 = (x1 << (r)) | (x1 >> (32 - (r))); x1 ^= x0; }
  x0 += k0;  x1 += k1;
  TFR(13) TFR(15) TFR(26) TFR(6)
  x0 += k1;  x1 += ks2 + 1u;
  TFR(17) TFR(29) TFR(16) TFR(24)
  x0 += ks2; x1 += k0 + 2u;
  TFR(13) TFR(15) TFR(26) TFR(6)
  x0 += k0;  x1 += k1 + 3u;
  TFR(17) TFR(29) TFR(16) TFR(24)
  x0 += k1;  x1 += ks2 + 4u;
  TFR(13) TFR(15) TFR(26) TFR(6)
  x0 += ks2; x1 += k0 + 5u;
#undef TFR
  *o0 = x0; *o1 = x1;
}

// Giles/XLA erfinv (same coefficients as XLA ErfInv32)
__device__ __forceinline__ float erfinv_f(float x)
{
  float w = -log1pf(-x * x);
  float p;
  if (w < 5.0f) {
    w = w - 2.5f;
    p = 2.81022636e-08f;
    p = fmaf(p, w, 3.43273939e-07f);
    p = fmaf(p, w, -3.5233877e-06f);
    p = fmaf(p, w, -4.39150654e-06f);
    p = fmaf(p, w, 0.00021858087f);
    p = fmaf(p, w, -0.00125372503f);
    p = fmaf(p, w, -0.00417768164f);
    p = fmaf(p, w, 0.246640727f);
    p = fmaf(p, w, 1.50140941f);
  } else {
    w = sqrtf(w) - 3.0f;
    p = -0.000200214257f;
    p = fmaf(p, w, 0.000100950558f);
    p = fmaf(p, w, 0.00134934322f);
    p = fmaf(p, w, -0.00367342844f);
    p = fmaf(p, w, 0.00573950773f);
    p = fmaf(p, w, -0.0076224613f);
    p = fmaf(p, w, 0.00943887047f);
    p = fmaf(p, w, 1.00167406f);
    p = fmaf(p, w, 2.83297682f);
  }
  return p * x;
}

__device__ __forceinline__ float bits_to_normal(unsigned bits)
{
  float u = __uint_as_float((bits >> 9) | 0x3f800000u) - 1.0f;
  const float lo = -0.99999994f;
  float v = fmaxf(lo, u * 2.0f + lo);
  return 1.41421356237f * erfinv_f(v);
}

// PARTITIONABLE threefry: (y0,y1) = threefry(key; 0, j); 32-bit draw = y0 ^ y1.
__device__ __forceinline__ float jax_normal_elem(unsigned k0, unsigned k1, unsigned j)
{
  unsigned y0, y1;
  threefry2x32(k0, k1, 0u, j, &y0, &y1);
  return bits_to_normal(y0 ^ y1);
}

// ---------------------------------------------------------------------------
// se3_exp (matches reference element-by-element)
// ---------------------------------------------------------------------------
__device__ __forceinline__ void mat3mul(const float* A, const float* Bm, float* Cm)
{
#pragma unroll
  for (int i = 0; i < 3; i++)
#pragma unroll
    for (int j = 0; j < 3; j++)
      Cm[i * 3 + j] = A[i * 3 + 0] * Bm[0 * 3 + j] + A[i * 3 + 1] * Bm[1 * 3 + j] + A[i * 3 + 2] * Bm[2 * 3 + j];
}

__device__ void se3_exp6(const float xi[6], float T[16])
{
  float tx = xi[0], ty = xi[1], tz = xi[2];
  float wx = xi[3], wy = xi[4], wz = xi[5];
  float theta = fmaxf(sqrtf(wx * wx + wy * wy + wz * wz), 1e-8f);
  float kx = wx / theta, ky = wy / theta, kz = wz / theta;
  float K[9] = { 0.f, -kz, ky,  kz, 0.f, -kx,  -ky, kx, 0.f };
  float KK[9];
  mat3mul(K, K, KK);
  float st = sinf(theta);
  float ct = 1.0f - cosf(theta);
  float a  = ct / theta;
  float bb = 1.0f - st / theta;
  float R[9], V[9];
#pragma unroll
  for (int i = 0; i < 9; i++) {
    float e = (i == 0 || i == 4 || i == 8) ? 1.0f : 0.0f;
    R[i] = e + st * K[i] + ct * KK[i];
    V[i] = e + a  * K[i] + bb * KK[i];
  }
  float tox = V[0] * tx + V[1] * ty + V[2] * tz;
  float toy = V[3] * tx + V[4] * ty + V[5] * tz;
  float toz = V[6] * tx + V[7] * ty + V[8] * tz;
  T[0] = R[0]; T[1] = R[1]; T[2]  = R[2]; T[3]  = tox;
  T[4] = R[3]; T[5] = R[4]; T[6]  = R[5]; T[7]  = toy;
  T[8] = R[6]; T[9] = R[7]; T[10] = R[8]; T[11] = toz;
  T[12] = 0.f; T[13] = 0.f; T[14] = 0.f; T[15] = 1.f;
}

// Apply LM delta for item bm (= b*16+m): T_out = se3_exp(step) @ T_in
__device__ __forceinline__ void apply_update(
    float Tm[16], int bm, int noise_iter, float damping, float res)
{
  const float* nz = g_noise + ((size_t)(noise_iter * (B_SZ * M16) + bm)) * 6;
  float s1 = -damping * res * 0.01f;
  float xi[6];
#pragma unroll
  for (int k = 0; k < 6; k++) xi[k] = s1 * nz[k];
  float D[16];
  se3_exp6(xi, D);
  float Told[16];
#pragma unroll
  for (int t = 0; t < 16; t++) Told[t] = Tm[t];
#pragma unroll
  for (int r = 0; r < 4; r++)
#pragma unroll
    for (int cc = 0; cc < 4; cc++)
      Tm[r * 4 + cc] = D[r * 4 + 0] * Told[0 * 4 + cc] + D[r * 4 + 1] * Told[1 * 4 + cc]
                     + D[r * 4 + 2] * Told[2 * 4 + cc] + D[r * 4 + 3] * Told[3 * 4 + cc];
}

// ---------------------------------------------------------------------------
// Transpose helper: one 32x32 tile of D = q - r, (B,C,HW) -> (B,HW,C), fp32
// ---------------------------------------------------------------------------
__device__ __forceinline__ void do_tile(
    const float* __restrict__ q, const float* __restrict__ r,
    float* __restrict__ Dt, int C, int HW,
    int b, int c0, int hw0, float* tile /* [32][33] */)
{
  const float* qb = q + (size_t)b * C * HW;
  const float* rb = r + (size_t)b * C * HW;
  float* Db = Dt + (size_t)b * HW * C;
  int tx = threadIdx.x & 31, ty = threadIdx.x >> 5;
#pragma unroll
  for (int i = ty; i < 32; i += 8) {
    int c = c0 + i, hw = hw0 + tx;
    tile[i * 33 + tx] = qb[(size_t)c * HW + hw] - rb[(size_t)c * HW + hw];
  }
  __syncthreads();
  int tid = threadIdx.x;
#pragma unroll
  for (int idx = tid; idx < 32 * 16; idx += 256) {
    int row = idx >> 4;
    int pr  = idx & 15;
    float2 h = make_float2(tile[(2 * pr) * 33 + row], tile[(2 * pr + 1) * 33 + row]);
    *(float2*)(Db + (size_t)(hw0 + row) * C + c0 + 2 * pr) = h;
  }
}

// ---------------------------------------------------------------------------
// prep A: blocks [0,8) = hypotheses; block 8 = noise; rest = L0 tiles
// ---------------------------------------------------------------------------
__global__ __launch_bounds__(256) void prep_kernel_A(
    const float* __restrict__ q0, const float* __restrict__ r0,
    float* __restrict__ D0,
    const float* __restrict__ Tpred, unsigned k0, unsigned k1)
{
  __shared__ float tile[32 * 33];
  int blk = blockIdx.x;
  if (blk < B_SZ) {
    int m = threadIdx.x;
    int b = blk;
    if (m >= M_HYP) return;
    float xi[6];
#pragma unroll
    for (int k = 0; k < 3; k++)
      xi[k] = jax_normal_elem(k0, k1, (unsigned)(m * 3 + k));
    int pi = m / 12, yj = m % 12;
    const float D2R = (float)(3.14159265358979323846 / 180.0);
    xi[3] = 0.0f;
    xi[4] = (-11.0f + 2.0f * (float)pi) * D2R;
    xi[5] = (-11.0f + 2.0f * (float)yj) * D2R;
    float dT[16];
    se3_exp6(xi, dT);
    const float* P = Tpred + b * 16;
    size_t off = (size_t)(b * M_HYP + m) * 16;
#pragma unroll
    for (int i = 0; i < 4; i++)
#pragma unroll
      for (int j = 0; j < 4; j++) {
        float v = dT[i * 4 + 0] * P[0 * 4 + j] + dT[i * 4 + 1] * P[1 * 4 + j]
                + dT[i * 4 + 2] * P[2 * 4 + j] + dT[i * 4 + 3] * P[3 * 4 + j];
        g_Tbuf[0][off + i * 4 + j] = v;
        g_Tbuf[1][off + i * 4 + j] = v;
      }
    return;
  }
  blk -= B_SZ;
  if (blk == 0) {
    const int LI[N_ITER] = {100, 101, 110, 111, 112, 120, 121, 122, 123};
    int tid = threadIdx.x;
    for (int it = 0; it < N_ITER; it++) {
      unsigned ik0, ik1;
      threefry2x32(0u, 42u, 0u, (unsigned)LI[it], &ik0, &ik1);
      for (int idx = tid; idx < B_SZ * M16 * 6; idx += 256) {
        int i = idx / 6, k = idx % 6;
        int b = i >> 4, m = i & 15;
        unsigned j = (unsigned)((b * M_HYP + m) * 6 + k);
        g_noise[it * (B_SZ * M16 * 6) + idx] = jax_normal_elem(ik0, ik1, j);
      }
    }
    return;
  }
  blk -= 1;
  {
    const int HWT = H0 * W0 / 32, CT = C0 / 32;
    int b = blk / (HWT * CT);
    int rem = blk % (HWT * CT);
    int c0 = (rem / HWT) * 32, hw0 = (rem % HWT) * 32;
    do_tile(q0, r0, D0, C0, H0 * W0, b, c0, hw0, tile);
  }
}

// ---------------------------------------------------------------------------
// prep B: L1 + L2 tiles (overlapped with the two L0 residual iterations)
// ---------------------------------------------------------------------------
__global__ __launch_bounds__(256) void prep_kernel_B(
    const float* __restrict__ q1, const float* __restrict__ r1,
    const float* __restrict__ q2, const float* __restrict__ r2,
    float* __restrict__ D1, float* __restrict__ D2)
{
  __shared__ float tile[32 * 33];
  int blk = blockIdx.x;
  if (blk < T1_TILES) {
    const int HWT = H1 * W1 / 32, CT = C1 / 32;
    int b = blk / (HWT * CT);
    int rem = blk % (HWT * CT);
    int c0 = (rem / HWT) * 32, hw0 = (rem % HWT) * 32;
    do_tile(q1, r1, D1, C1, H1 * W1, b, c0, hw0, tile);
    return;
  }
  blk -= T1_TILES;
  {
    const int HWT = H2 * W2 / 32;
    int b = blk / HWT;
    int hw0 = (blk % HWT) * 32;
    do_tile(q2, r2, D2, C2, H2 * W2, b, 0, hw0, tile);
  }
}

// ---------------------------------------------------------------------------
// Residual kernel with fused per-bm LM update prologue (per-thread redundant).
// grid = B*16*PS = 1024 blocks, 256 threads (8 warps). Natural regs.
// Warp w owns points n = slice*63 + w + 8*p (p = 0..vc-1, vc <= 8).
// Lane l (l<8) projects point p=l; then channel loop broadcasts each point
// with a 1-deep software prefetch pipeline. D is fp32: no conversions.
// ---------------------------------------------------------------------------
template <int CPL>
__global__ __launch_bounds__(256) void residual_kernel(
    const float* __restrict__ Dt, const float* __restrict__ Umap,
    const float* __restrict__ geo, const float* __restrict__ Kin,
    int C, int H, int W, float scale, int iter, float damping_prev)
{
  int bm    = blockIdx.x >> 3;
  int slice = blockIdx.x & 7;
  int b = bm >> 4, m = bm & 15;
  int lane = threadIdx.x & 31, w = threadIdx.x >> 5;
  int rp = (iter + 1) & 1, wq = iter & 1;

  // ---- prologue: compute T_iter for this bm (redundant across threads) ----
  float Tm[16];
  {
    const float* Tsrc = g_Tbuf[rp] + (size_t)(b * M_HYP + m) * 16;
#pragma unroll
    for (int i = 0; i < 16; i++) Tm[i] = Tsrc[i];
    if (iter > 0) {
      float rs = 0.0f;
#pragma unroll
      for (int p = 0; p < PS; p++) rs += g_resacc[rp][p][bm];
      float res = rs * (1.0f / N_PTS);
      apply_update(Tm, bm, iter - 1, damping_prev, res);
      if (threadIdx.x < 16 && slice == 0)
        g_Tbuf[wq][(size_t)(b * M_HYP + m) * 16 + threadIdx.x] = Tm[threadIdx.x];
    }
  }

  float T00 = Tm[0], T01 = Tm[1], T02 = Tm[2],  T03 = Tm[3];
  float T10 = Tm[4], T11 = Tm[5], T12 = Tm[6],  T13 = Tm[7];
  float T20 = Tm[8], T21 = Tm[9], T22 = Tm[10], T23 = Tm[11];
  float fx = __ldg(Kin + b * 9 + 0) * scale, cx = __ldg(Kin + b * 9 + 2) * scale;
  float fy = __ldg(Kin + b * 9 + 4) * scale, cy = __ldg(Kin + b * 9 + 5) * scale;
  const float* Db = Dt + (size_t)b * H * W * C;
  const float* Ub = Umap + (size_t)b * H * W;
  const float* G  = geo + (size_t)b * N_PTS * 3;

  // ---- projection: lane l projects point slice*63 + w + 8*l ----
  float Wm1 = (float)(W - 1), Hm1 = (float)(H - 1);
  int nbeg = slice * 63 + w;
  int nend = min(N_PTS, slice * 63 + 63);
  int vc = (nend - nbeg + 7) >> 3;               // 1..8 points for this warp
  int n = min(nbeg + 8 * (lane & 7), N_PTS - 1);
  int o00, o01, o10, o11;
  float w00, w01, w10, w11, us;
  {
    float X = __ldg(G + n * 3 + 0);
    float Y = __ldg(G + n * 3 + 1);
    float Z = __ldg(G + n * 3 + 2);
    float px = T00 * X + T01 * Y + T02 * Z + T03;
    float py = T10 * X + T11 * Y + T12 * Z + T13;
    float pz = T20 * X + T21 * Y + T22 * Z + T23;
    float z  = fmaxf(pz, 1e-6f);
    float u  = fx * (px / z) + cx;
    float v  = fy * (py / z) + cy;
    float gx = 2.0f * u / Wm1 - 1.0f;
    float gy = 2.0f * v / Hm1 - 1.0f;
    float xs = fminf(fmaxf(((gx + 1.0f) * (float)W - 1.0f) * 0.5f, 0.0f), Wm1);
    float ys = fminf(fmaxf(((gy + 1.0f) * (float)H - 1.0f) * 0.5f, 0.0f), Hm1);
    float x0f = floorf(xs), y0f = floorf(ys);
    float x1f = fminf(x0f + 1.0f, Wm1), y1f = fminf(y0f + 1.0f, Hm1);
    float wx = xs - x0f, wy = ys - y0f;
    int x0 = (int)x0f, x1 = (int)x1f, y0 = (int)y0f, y1 = (int)y1f;
    w00 = (1.0f - wx) * (1.0f - wy); w01 = wx * (1.0f - wy);
    w10 = (1.0f - wx) * wy;          w11 = wx * wy;
    int r0 = y0 * W, r1 = y1 * W;
    us = w00 * __ldg(Ub + r0 + x0) + w01 * __ldg(Ub + r0 + x1)
       + w10 * __ldg(Ub + r1 + x0) + w11 * __ldg(Ub + r1 + x1);
    o00 = (r0 + x0) * 32; o01 = (r0 + x1) * 32;
    o10 = (r1 + x0) * 32; o11 = (r1 + x1) * 32;
  }

  float wacc = 0.0f;

  if constexpr (CPL == 4) {
    const float4* base = (const float4*)Db;
    float4 ca, cb, cc2, cd;
    float cw00, cw01, cw10, cw11, cus;
    {
      int a00 = __shfl_sync(0xffffffffu, o00, 0), a01 = __shfl_sync(0xffffffffu, o01, 0);
      int a10 = __shfl_sync(0xffffffffu, o10, 0), a11 = __shfl_sync(0xffffffffu, o11, 0);
      cw00 = __shfl_sync(0xffffffffu, w00, 0); cw01 = __shfl_sync(0xffffffffu, w01, 0);
      cw10 = __shfl_sync(0xffffffffu, w10, 0); cw11 = __shfl_sync(0xffffffffu, w11, 0);
      cus  = __shfl_sync(0xffffffffu, us,  0);
      ca = __ldg(base + a00 + lane); cb = __ldg(base + a01 + lane);
      cc2 = __ldg(base + a10 + lane); cd = __ldg(base + a11 + lane);
    }
    for (int p = 0; p < vc; p++) {
      float4 na = {}, nb = {}, nc = {}, nd = {};
      float nw00 = 0, nw01 = 0, nw10 = 0, nw11 = 0, nus = 0;
      if (p + 1 < vc) {
        int a00 = __shfl_sync(0xffffffffu, o00, p + 1), a01 = __shfl_sync(0xffffffffu, o01, p + 1);
        int a10 = __shfl_sync(0xffffffffu, o10, p + 1), a11 = __shfl_sync(0xffffffffu, o11, p + 1);
        nw00 = __shfl_sync(0xffffffffu, w00, p + 1); nw01 = __shfl_sync(0xffffffffu, w01, p + 1);
        nw10 = __shfl_sync(0xffffffffu, w10, p + 1); nw11 = __shfl_sync(0xffffffffu, w11, p + 1);
        nus  = __shfl_sync(0xffffffffu, us,  p + 1);
        na = __ldg(base + a00 + lane); nb = __ldg(base + a01 + lane);
        nc = __ldg(base + a10 + lane); nd = __ldg(base + a11 + lane);
      }
      float e0 = cw00 * ca.x; e0 = fmaf(cw01, cb.x, e0); e0 = fmaf(cw10, cc2.x, e0); e0 = fmaf(cw11, cd.x, e0);
      float e1 = cw00 * ca.y; e1 = fmaf(cw01, cb.y, e1); e1 = fmaf(cw10, cc2.y, e1); e1 = fmaf(cw11, cd.y, e1);
      float e2 = cw00 * ca.z; e2 = fmaf(cw01, cb.z, e2); e2 = fmaf(cw10, cc2.z, e2); e2 = fmaf(cw11, cd.z, e2);
      float e3 = cw00 * ca.w; e3 = fmaf(cw01, cb.w, e3); e3 = fmaf(cw10, cc2.w, e3); e3 = fmaf(cw11, cd.w, e3);
      float spt = e0 * e0 + e1 * e1 + e2 * e2 + e3 * e3;
      wacc = fmaf(cus, spt, wacc);
      ca = na; cb = nb; cc2 = nc; cd = nd;
      cw00 = nw00; cw01 = nw01; cw10 = nw10; cw11 = nw11; cus = nus;
    }
  } else if constexpr (CPL == 2) {
    const float2* base = (const float2*)Db;
    float2 ca, cb, cc2, cd;
    float cw00, cw01, cw10, cw11, cus;
    {
      int a00 = __shfl_sync(0xffffffffu, o00, 0), a01 = __shfl_sync(0xffffffffu, o01, 0);
      int a10 = __shfl_sync(0xffffffffu, o10, 0), a11 = __shfl_sync(0xffffffffu, o11, 0);
      cw00 = __shfl_sync(0xffffffffu, w00, 0); cw01 = __shfl_sync(0xffffffffu, w01, 0);
      cw10 = __shfl_sync(0xffffffffu, w10, 0); cw11 = __shfl_sync(0xffffffffu, w11, 0);
      cus  = __shfl_sync(0xffffffffu, us,  0);
      ca = __ldg(base + a00 + lane); cb = __ldg(base + a01 + lane);
      cc2 = __ldg(base + a10 + lane); cd = __ldg(base + a11 + lane);
    }
    for (int p = 0; p < vc; p++) {
      float2 na = {}, nb = {}, nc = {}, nd = {};
      float nw00 = 0, nw01 = 0, nw10 = 0, nw11 = 0, nus = 0;
      if (p + 1 < vc) {
        int a00 = __shfl_sync(0xffffffffu, o00, p + 1), a01 = __shfl_sync(0xffffffffu, o01, p + 1);
        int a10 = __shfl_sync(0xffffffffu, o10, p + 1), a11 = __shfl_sync(0xffffffffu, o11, p + 1);
        nw00 = __shfl_sync(0xffffffffu, w00, p + 1); nw01 = __shfl_sync(0xffffffffu, w01, p + 1);
        nw10 = __shfl_sync(0xffffffffu, w10, p + 1); nw11 = __shfl_sync(0xffffffffu, w11, p + 1);
        nus  = __shfl_sync(0xffffffffu, us,  p + 1);
        na = __ldg(base + a00 + lane); nb = __ldg(base + a01 + lane);
        nc = __ldg(base + a10 + lane); nd = __ldg(base + a11 + lane);
      }
      float e0 = cw00 * ca.x; e0 = fmaf(cw01, cb.x, e0); e0 = fmaf(cw10, cc2.x, e0); e0 = fmaf(cw11, cd.x, e0);
      float e1 = cw00 * ca.y; e1 = fmaf(cw01, cb.y, e1); e1 = fmaf(cw10, cc2.y, e1); e1 = fmaf(cw11, cd.y, e1);
      float spt = e0 * e0 + e1 * e1;
      wacc = fmaf(cus, spt, wacc);
      ca = na; cb = nb; cc2 = nc; cd = nd;
      cw00 = nw00; cw01 = nw01; cw10 = nw10; cw11 = nw11; cus = nus;
    }
  } else {
    float ca, cb, cc2, cd;
    float cw00, cw01, cw10, cw11, cus;
    {
      int a00 = __shfl_sync(0xffffffffu, o00, 0), a01 = __shfl_sync(0xffffffffu, o01, 0);
      int a10 = __shfl_sync(0xffffffffu, o10, 0), a11 = __shfl_sync(0xffffffffu, o11, 0);
      cw00 = __shfl_sync(0xffffffffu, w00, 0); cw01 = __shfl_sync(0xffffffffu, w01, 0);
      cw10 = __shfl_sync(0xffffffffu, w10, 0); cw11 = __shfl_sync(0xffffffffu, w11, 0);
      cus  = __shfl_sync(0xffffffffu, us,  0);
      ca = __ldg(Db + a00 + lane); cb = __ldg(Db + a01 + lane);
      cc2 = __ldg(Db + a10 + lane); cd = __ldg(Db + a11 + lane);
    }
    for (int p = 0; p < vc; p++) {
      float na = 0.f, nb = 0.f, nc = 0.f, nd = 0.f;
      float nw00 = 0, nw01 = 0, nw10 = 0, nw11 = 0, nus = 0;
      if (p + 1 < vc) {
        int a00 = __shfl_sync(0xffffffffu, o00, p + 1), a01 = __shfl_sync(0xffffffffu, o01, p + 1);
        int a10 = __shfl_sync(0xffffffffu, o10, p + 1), a11 = __shfl_sync(0xffffffffu, o11, p + 1);
        nw00 = __shfl_sync(0xffffffffu, w00, p + 1); nw01 = __shfl_sync(0xffffffffu, w01, p + 1);
        nw10 = __shfl_sync(0xffffffffu, w10, p + 1); nw11 = __shfl_sync(0xffffffffu, w11, p + 1);
        nus  = __shfl_sync(0xffffffffu, us,  p + 1);
        na = __ldg(Db + a00 + lane); nb = __ldg(Db + a01 + lane);
        nc = __ldg(Db + a10 + lane); nd = __ldg(Db + a11 + lane);
      }
      float e0 = cw00 * ca;
      e0 = fmaf(cw01, cb, e0);
      e0 = fmaf(cw10, cc2, e0);
      e0 = fmaf(cw11, cd, e0);
      float spt = e0 * e0;
      wacc = fmaf(cus, spt, wacc);
      ca = na; cb = nb; cc2 = nc; cd = nd;
      cw00 = nw00; cw01 = nw01; cw10 = nw10; cw11 = nw11; cus = nus;
    }
  }

#pragma unroll
  for (int o = 16; o; o >>= 1) wacc += __shfl_xor_sync(0xffffffffu, wacc, o);
  __shared__ float wpar[8];
  if (lane == 0) wpar[w] = wacc;
  __syncthreads();
  if (threadIdx.x == 0) {
    float s = 0.0f;
#pragma unroll
    for (int ww = 0; ww < 8; ww++) s += wpar[ww];
    g_resacc[wq][slice][bm] = s;
  }
}

// ---------------------------------------------------------------------------
// final kernel: applies the 9th LM update, then geodesic + argmin + output.
// grid = B blocks x 144 threads. After iter 8: T_8 in g_Tbuf[0], res_8 in
// g_resacc[0].
// ---------------------------------------------------------------------------
__global__ void final_kernel(const float* __restrict__ Tpred, float* __restrict__ out,
                             float damping_last)
{
  int b = blockIdx.x;
  int m = threadIdx.x;
  __shared__ float tot[M_HYP];
  if (m < M_HYP) {
    float Tc[16];
    const float* Tsrc = g_Tbuf[0] + (size_t)(b * M_HYP + m) * 16;
#pragma unroll
    for (int i = 0; i < 16; i++) Tc[i] = Tsrc[i];
    float c = 0.0f;
    if (m < M16) {
      int bm = b * M16 + m;
      float rs = 0.0f;
#pragma unroll
      for (int p = 0; p < PS; p++) rs += g_resacc[0][p][bm];
      c = rs * (1.0f / N_PTS);
      apply_update(Tc, bm, 8, damping_last, c);
    }
    const float* P = Tpred + b * 16;
    float Ri[9] = { P[0], P[4], P[8],  P[1], P[5], P[9],  P[2], P[6], P[10] };
    float tix = -(Ri[0] * P[3] + Ri[1] * P[7] + Ri[2] * P[11]);
    float tiy = -(Ri[3] * P[3] + Ri[4] * P[7] + Ri[5] * P[11]);
    float tiz = -(Ri[6] * P[3] + Ri[7] * P[7] + Ri[8] * P[11]);
    float Ti[16] = { Ri[0], Ri[1], Ri[2], tix,
                     Ri[3], Ri[4], Ri[5], tiy,
                     Ri[6], Ri[7], Ri[8], tiz,
                     0.f, 0.f, 0.f, 1.f };
    float A[16];
#pragma unroll
    for (int i = 0; i < 4; i++)
#pragma unroll
      for (int j = 0; j < 4; j++)
        A[i * 4 + j] = Tc[i * 4 + 0] * Ti[0 * 4 + j] + Tc[i * 4 + 1] * Ti[1 * 4 + j]
                     + Tc[i * 4 + 2] * Ti[2 * 4 + j] + Tc[i * 4 + 3] * Ti[3 * 4 + j];
    float cos_a = (A[0] + A[5] + A[10] - 1.0f) * 0.5f;
    const float CL = (float)(1.0 - 1e-7);
    cos_a = fminf(fmaxf(cos_a, -CL), CL);
    float theta = acosf(cos_a);
    float th = fmaxf(theta, 1e-8f);
    float sn = fmaxf(sinf(th), 1e-8f);
    float wx = (A[9] - A[6]) / (2.0f * sn) * th;
    float wy = (A[2] - A[8]) / (2.0f * sn) * th;
    float wz = (A[4] - A[1]) / (2.0f * sn) * th;
    if (fabsf(theta) < 1e-6f) { wx = 0.f; wy = 0.f; wz = 0.f; }
    float tx = A[3], ty = A[7], tz = A[11];
    float geod = sqrtf(tx * tx + ty * ty + tz * tz + wx * wx + wy * wy + wz * wz);
    tot[m] = c + geod;
    out[128 + b * M_HYP + m] = c;
    float* Tdst = g_Tbuf[1] + (size_t)(b * M_HYP + m) * 16;
#pragma unroll
    for (int i = 0; i < 16; i++) Tdst[i] = Tc[i];
  }
  __syncthreads();
  if (m == 0) {
    int best = 0;
    float bv = tot[0];
    for (int i = 1; i < M_HYP; i++)
      if (tot[i] < bv) { bv = tot[i]; best = i; }
    const float* Tb = g_Tbuf[1] + (size_t)(b * M_HYP + best) * 16;
#pragma unroll
    for (int i = 0; i < 16; i++) out[b * 16 + i] = Tb[i];
  }
}

// ---------------------------------------------------------------------------
// Host launch
// ---------------------------------------------------------------------------
extern "C" void kernel_launch(void* const* d_in, const int* in_sizes, int n_in,
                              void* d_out, int out_size)
{
  const float* T_pred = (const float*)d_in[0];
  const float* geo    = (const float*)d_in[1];
  const float* Kin    = (const float*)d_in[2];
  const float* q0 = (const float*)d_in[3];
  const float* q1 = (const float*)d_in[4];
  const float* q2 = (const float*)d_in[5];
  const float* r0 = (const float*)d_in[6];
  const float* r1 = (const float*)d_in[7];
  const float* r2 = (const float*)d_in[8];
  const float* u0 = (const float*)d_in[9];
  const float* u1 = (const float*)d_in[10];
  const float* u2 = (const float*)d_in[11];
  float* out = (float*)d_out;

  float *D0p, *D1p, *D2p;
  cudaGetSymbolAddress((void**)&D0p, g_D0);
  cudaGetSymbolAddress((void**)&D1p, g_D1);
  cudaGetSymbolAddress((void**)&D2p, g_D2);

  // side stream + events (created once, on the uncaptured correctness call)
  static cudaStream_t s2 = nullptr;
  static cudaEvent_t evFork = nullptr, evJoin = nullptr;
  static bool tried = false;
  if (!tried) {
    tried = true;
    if (cudaStreamCreateWithFlags(&s2, cudaStreamNonBlocking) != cudaSuccess) s2 = nullptr;
    if (cudaEventCreateWithFlags(&evFork, cudaEventDisableTiming) != cudaSuccess) evFork = nullptr;
    if (cudaEventCreateWithFlags(&evJoin, cudaEventDisableTiming) != cudaSuccess) evJoin = nullptr;
  }
  bool use2 = (s2 && evFork && evJoin);

  unsigned hk0, hk1;
  threefry2x32(0u, 42u, 0u, 0u, &hk0, &hk1);

  // prep A (hyp + noise + L0) on main stream; prep B (L1+L2) overlapped on s2
  if (use2) {
    cudaEventRecord(evFork, 0);
    cudaStreamWaitEvent(s2, evFork, 0);
    prep_kernel_B<<<T1_TILES + T2_TILES, 256, 0, s2>>>(q1, r1, q2, r2, D1p, D2p);
    cudaEventRecord(evJoin, s2);
  } else {
    prep_kernel_B<<<T1_TILES + T2_TILES, 256>>>(q1, r1, q2, r2, D1p, D2p);
  }
  prep_kernel_A<<<B_SZ + 1 + T0_TILES, 256>>>(q0, r0, D0p, T_pred, hk0, hk1);

  const int   lvl[N_ITER]  = {0, 0, 1, 1, 1, 2, 2, 2, 2};
  const float damp[3]      = {0.001f, 0.0005f, 0.00025f};
  const int   grid_res = B_SZ * M16 * PS;    // 1024 blocks
  for (int k = 0; k < N_ITER; k++) {
    int level = lvl[k];
    if (k == 2 && use2) cudaStreamWaitEvent(0, evJoin, 0);   // join before L1 use
    float scale = 1.0f / (4.0f / (float)(1 << level));
    float dprev = (k > 0) ? damp[lvl[k - 1]] : 0.0f;
    if (level == 0)
      residual_kernel<4><<<grid_res, 256>>>(D0p, u0, geo, Kin, C0, H0, W0, scale, k, dprev);
    else if (level == 1)
      residual_kernel<2><<<grid_res, 256>>>(D1p, u1, geo, Kin, C1, H1, W1, scale, k, dprev);
    else
      residual_kernel<1><<<grid_res, 256>>>(D2p, u2, geo, Kin, C2, H2, W2, scale, k, dprev);
  }

  final_kernel<<<B_SZ, M_HYP>>>(T_pred, out, damp[2]);
  (void)in_sizes; (void)n_in; (void)out_size;
}

// round 15
// speedup vs baseline: 1.0942x; 1.0942x over previous
#include <cuda_runtime.h>
#include <cuda_bf16.h>
#include <math.h>

// ---------------------------------------------------------------------------
// Problem dimensions (fixed by the reference setup)
// ---------------------------------------------------------------------------
#define B_SZ   8
#define N_PTS  500
#define M_HYP  144
#define M16    16
#define PS     8           // point slices per (b,m): 63 points each (last: 59)
#define N_ITER 9

#define C0 128
#define H0 48
#define W0 64
#define C1 64
#define H1 96
#define W1 128
#define C2 32
#define H2 192
#define W2 256

// transpose tile counts (32x32 tiles)
#define T0_TILES ((H0*W0/32) * (C0/32) * B_SZ)   // 3072
#define T1_TILES ((H1*W1/32) * (C1/32) * B_SZ)   // 6144
#define T2_TILES ((H2*W2/32) * (C2/32) * B_SZ)   // 12288

// ---------------------------------------------------------------------------
// Scratch (__device__ globals — no allocation allowed). D stored as bf16
// (round-14 lesson: bf16 halves prefetch register footprint; occupancy wins).
// ---------------------------------------------------------------------------
__device__ __nv_bfloat16 g_D0[(size_t)B_SZ * H0 * W0 * C0];   // q0-r0, channel-last
__device__ __nv_bfloat16 g_D1[(size_t)B_SZ * H1 * W1 * C1];
__device__ __nv_bfloat16 g_D2[(size_t)B_SZ * H2 * W2 * C2];
__device__ float g_Tbuf[2][B_SZ * M_HYP * 16];       // double-buffered poses
__device__ float g_resacc[2][PS][B_SZ * M16];         // double-buffered partial residuals
__device__ float g_noise[N_ITER * B_SZ * M16 * 6];    // precomputed LM noise (m<16 only)

// ---------------------------------------------------------------------------
// Threefry-2x32 (exactly JAX's 20-round schedule; KAT-verified)
// ---------------------------------------------------------------------------
__host__ __device__ __forceinline__ void threefry2x32(
    unsigned k0, unsigned k1, unsigned x0, unsigned x1,
    unsigned* o0, unsigned* o1)
{
  unsigned ks2 = k0 ^ k1 ^ 0x1BD11BDAu;
#define TFR(r) { x0 += x1; x1 = (x1 << (r)) | (x1 >> (32 - (r))); x1 ^= x0; }
  x0 += k0;  x1 += k1;
  TFR(13) TFR(15) TFR(26) TFR(6)
  x0 += k1;  x1 += ks2 + 1u;
  TFR(17) TFR(29) TFR(16) TFR(24)
  x0 += ks2; x1 += k0 + 2u;
  TFR(13) TFR(15) TFR(26) TFR(6)
  x0 += k0;  x1 += k1 + 3u;
  TFR(17) TFR(29) TFR(16) TFR(24)
  x0 += k1;  x1 += ks2 + 4u;
  TFR(13) TFR(15) TFR(26) TFR(6)
  x0 += ks2; x1 += k0 + 5u;
#undef TFR
  *o0 = x0; *o1 = x1;
}

// Giles/XLA erfinv (same coefficients as XLA ErfInv32)
__device__ __forceinline__ float erfinv_f(float x)
{
  float w = -log1pf(-x * x);
  float p;
  if (w < 5.0f) {
    w = w - 2.5f;
    p = 2.81022636e-08f;
    p = fmaf(p, w, 3.43273939e-07f);
    p = fmaf(p, w, -3.5233877e-06f);
    p = fmaf(p, w, -4.39150654e-06f);
    p = fmaf(p, w, 0.00021858087f);
    p = fmaf(p, w, -0.00125372503f);
    p = fmaf(p, w, -0.00417768164f);
    p = fmaf(p, w, 0.246640727f);
    p = fmaf(p, w, 1.50140941f);
  } else {
    w = sqrtf(w) - 3.0f;
    p = -0.000200214257f;
    p = fmaf(p, w, 0.000100950558f);
    p = fmaf(p, w, 0.00134934322f);
    p = fmaf(p, w, -0.00367342844f);
    p = fmaf(p, w, 0.00573950773f);
    p = fmaf(p, w, -0.0076224613f);
    p = fmaf(p, w, 0.00943887047f);
    p = fmaf(p, w, 1.00167406f);
    p = fmaf(p, w, 2.83297682f);
  }
  return p * x;
}

__device__ __forceinline__ float bits_to_normal(unsigned bits)
{
  float u = __uint_as_float((bits >> 9) | 0x3f800000u) - 1.0f;
  const float lo = -0.99999994f;
  float v = fmaxf(lo, u * 2.0f + lo);
  return 1.41421356237f * erfinv_f(v);
}

// PARTITIONABLE threefry: (y0,y1) = threefry(key; 0, j); 32-bit draw = y0 ^ y1.
__device__ __forceinline__ float jax_normal_elem(unsigned k0, unsigned k1, unsigned j)
{
  unsigned y0, y1;
  threefry2x32(k0, k1, 0u, j, &y0, &y1);
  return bits_to_normal(y0 ^ y1);
}

// ---------------------------------------------------------------------------
// se3_exp (matches reference element-by-element)
// ---------------------------------------------------------------------------
__device__ __forceinline__ void mat3mul(const float* A, const float* Bm, float* Cm)
{
#pragma unroll
  for (int i = 0; i < 3; i++)
#pragma unroll
    for (int j = 0; j < 3; j++)
      Cm[i * 3 + j] = A[i * 3 + 0] * Bm[0 * 3 + j] + A[i * 3 + 1] * Bm[1 * 3 + j] + A[i * 3 + 2] * Bm[2 * 3 + j];
}

__device__ void se3_exp6(const float xi[6], float T[16])
{
  float tx = xi[0], ty = xi[1], tz = xi[2];
  float wx = xi[3], wy = xi[4], wz = xi[5];
  float theta = fmaxf(sqrtf(wx * wx + wy * wy + wz * wz), 1e-8f);
  float kx = wx / theta, ky = wy / theta, kz = wz / theta;
  float K[9] = { 0.f, -kz, ky,  kz, 0.f, -kx,  -ky, kx, 0.f };
  float KK[9];
  mat3mul(K, K, KK);
  float st = sinf(theta);
  float ct = 1.0f - cosf(theta);
  float a  = ct / theta;
  float bb = 1.0f - st / theta;
  float R[9], V[9];
#pragma unroll
  for (int i = 0; i < 9; i++) {
    float e = (i == 0 || i == 4 || i == 8) ? 1.0f : 0.0f;
    R[i] = e + st * K[i] + ct * KK[i];
    V[i] = e + a  * K[i] + bb * KK[i];
  }
  float tox = V[0] * tx + V[1] * ty + V[2] * tz;
  float toy = V[3] * tx + V[4] * ty + V[5] * tz;
  float toz = V[6] * tx + V[7] * ty + V[8] * tz;
  T[0] = R[0]; T[1] = R[1]; T[2]  = R[2]; T[3]  = tox;
  T[4] = R[3]; T[5] = R[4]; T[6]  = R[5]; T[7]  = toy;
  T[8] = R[6]; T[9] = R[7]; T[10] = R[8]; T[11] = toz;
  T[12] = 0.f; T[13] = 0.f; T[14] = 0.f; T[15] = 1.f;
}

// Apply LM delta for item bm (= b*16+m): T_out = se3_exp(step) @ T_in
__device__ __forceinline__ void apply_update(
    float Tm[16], int bm, int noise_iter, float damping, float res)
{
  const float* nz = g_noise + ((size_t)(noise_iter * (B_SZ * M16) + bm)) * 6;
  float s1 = -damping * res * 0.01f;
  float xi[6];
#pragma unroll
  for (int k = 0; k < 6; k++) xi[k] = s1 * nz[k];
  float D[16];
  se3_exp6(xi, D);
  float Told[16];
#pragma unroll
  for (int t = 0; t < 16; t++) Told[t] = Tm[t];
#pragma unroll
  for (int r = 0; r < 4; r++)
#pragma unroll
    for (int cc = 0; cc < 4; cc++)
      Tm[r * 4 + cc] = D[r * 4 + 0] * Told[0 * 4 + cc] + D[r * 4 + 1] * Told[1 * 4 + cc]
                     + D[r * 4 + 2] * Told[2 * 4 + cc] + D[r * 4 + 3] * Told[3 * 4 + cc];
}

// ---------------------------------------------------------------------------
// Transpose helper: one 32x32 tile of D = q - r, (B,C,HW) -> (B,HW,C), bf16
// ---------------------------------------------------------------------------
__device__ __forceinline__ void do_tile(
    const float* __restrict__ q, const float* __restrict__ r,
    __nv_bfloat16* __restrict__ Dt, int C, int HW,
    int b, int c0, int hw0, float* tile /* [32][33] */)
{
  const float* qb = q + (size_t)b * C * HW;
  const float* rb = r + (size_t)b * C * HW;
  __nv_bfloat16* Db = Dt + (size_t)b * HW * C;
  int tx = threadIdx.x & 31, ty = threadIdx.x >> 5;
#pragma unroll
  for (int i = ty; i < 32; i += 8) {
    int c = c0 + i, hw = hw0 + tx;
    tile[i * 33 + tx] = qb[(size_t)c * HW + hw] - rb[(size_t)c * HW + hw];
  }
  __syncthreads();
  int tid = threadIdx.x;
#pragma unroll
  for (int idx = tid; idx < 32 * 16; idx += 256) {
    int row = idx >> 4;
    int pr  = idx & 15;
    __nv_bfloat162 h = __floats2bfloat162_rn(tile[(2 * pr) * 33 + row],
                                             tile[(2 * pr + 1) * 33 + row]);
    *(__nv_bfloat162*)(Db + (size_t)(hw0 + row) * C + c0 + 2 * pr) = h;
  }
}

// ---------------------------------------------------------------------------
// prep A: blocks [0,8) = hypotheses; block 8 = noise; rest = L0 tiles
// ---------------------------------------------------------------------------
__global__ __launch_bounds__(256) void prep_kernel_A(
    const float* __restrict__ q0, const float* __restrict__ r0,
    __nv_bfloat16* __restrict__ D0,
    const float* __restrict__ Tpred, unsigned k0, unsigned k1)
{
  __shared__ float tile[32 * 33];
  int blk = blockIdx.x;
  if (blk < B_SZ) {
    int m = threadIdx.x;
    int b = blk;
    if (m >= M_HYP) return;
    float xi[6];
#pragma unroll
    for (int k = 0; k < 3; k++)
      xi[k] = jax_normal_elem(k0, k1, (unsigned)(m * 3 + k));
    int pi = m / 12, yj = m % 12;
    const float D2R = (float)(3.14159265358979323846 / 180.0);
    xi[3] = 0.0f;
    xi[4] = (-11.0f + 2.0f * (float)pi) * D2R;
    xi[5] = (-11.0f + 2.0f * (float)yj) * D2R;
    float dT[16];
    se3_exp6(xi, dT);
    const float* P = Tpred + b * 16;
    size_t off = (size_t)(b * M_HYP + m) * 16;
#pragma unroll
    for (int i = 0; i < 4; i++)
#pragma unroll
      for (int j = 0; j < 4; j++) {
        float v = dT[i * 4 + 0] * P[0 * 4 + j] + dT[i * 4 + 1] * P[1 * 4 + j]
                + dT[i * 4 + 2] * P[2 * 4 + j] + dT[i * 4 + 3] * P[3 * 4 + j];
        g_Tbuf[0][off + i * 4 + j] = v;
        g_Tbuf[1][off + i * 4 + j] = v;
      }
    return;
  }
  blk -= B_SZ;
  if (blk == 0) {
    const int LI[N_ITER] = {100, 101, 110, 111, 112, 120, 121, 122, 123};
    int tid = threadIdx.x;
    for (int it = 0; it < N_ITER; it++) {
      unsigned ik0, ik1;
      threefry2x32(0u, 42u, 0u, (unsigned)LI[it], &ik0, &ik1);
      for (int idx = tid; idx < B_SZ * M16 * 6; idx += 256) {
        int i = idx / 6, k = idx % 6;
        int b = i >> 4, m = i & 15;
        unsigned j = (unsigned)((b * M_HYP + m) * 6 + k);
        g_noise[it * (B_SZ * M16 * 6) + idx] = jax_normal_elem(ik0, ik1, j);
      }
    }
    return;
  }
  blk -= 1;
  {
    const int HWT = H0 * W0 / 32, CT = C0 / 32;
    int b = blk / (HWT * CT);
    int rem = blk % (HWT * CT);
    int c0 = (rem / HWT) * 32, hw0 = (rem % HWT) * 32;
    do_tile(q0, r0, D0, C0, H0 * W0, b, c0, hw0, tile);
  }
}

// ---------------------------------------------------------------------------
// prep B: L1 + L2 tiles (overlapped with the two L0 residual iterations)
// ---------------------------------------------------------------------------
__global__ __launch_bounds__(256) void prep_kernel_B(
    const float* __restrict__ q1, const float* __restrict__ r1,
    const float* __restrict__ q2, const float* __restrict__ r2,
    __nv_bfloat16* __restrict__ D1, __nv_bfloat16* __restrict__ D2)
{
  __shared__ float tile[32 * 33];
  int blk = blockIdx.x;
  if (blk < T1_TILES) {
    const int HWT = H1 * W1 / 32, CT = C1 / 32;
    int b = blk / (HWT * CT);
    int rem = blk % (HWT * CT);
    int c0 = (rem / HWT) * 32, hw0 = (rem % HWT) * 32;
    do_tile(q1, r1, D1, C1, H1 * W1, b, c0, hw0, tile);
    return;
  }
  blk -= T1_TILES;
  {
    const int HWT = H2 * W2 / 32;
    int b = blk / HWT;
    int hw0 = (blk % HWT) * 32;
    do_tile(q2, r2, D2, C2, H2 * W2, b, 0, hw0, tile);
  }
}

// ---------------------------------------------------------------------------
// Residual kernel with fused per-bm LM update prologue (per-thread redundant).
// grid = B*16*PS = 1024 blocks, 256 threads (8 warps). Natural regs (48).
// Warp w owns points n = slice*63 + w + 8*p (p = 0..vc-1, vc <= 8).
// Lane l (l<8) projects point p=l; then channel loop broadcasts each point
// with a 1-deep software prefetch pipeline.
// ---------------------------------------------------------------------------
template <int CPL>
__global__ __launch_bounds__(256) void residual_kernel(
    const __nv_bfloat16* __restrict__ Dt, const float* __restrict__ Umap,
    const float* __restrict__ geo, const float* __restrict__ Kin,
    int C, int H, int W, float scale, int iter, float damping_prev)
{
  int bm    = blockIdx.x >> 3;
  int slice = blockIdx.x & 7;
  int b = bm >> 4, m = bm & 15;
  int lane = threadIdx.x & 31, w = threadIdx.x >> 5;
  int rp = (iter + 1) & 1, wq = iter & 1;

  // ---- prologue: compute T_iter for this bm (redundant across threads) ----
  float Tm[16];
  {
    const float* Tsrc = g_Tbuf[rp] + (size_t)(b * M_HYP + m) * 16;
#pragma unroll
    for (int i = 0; i < 16; i++) Tm[i] = Tsrc[i];
    if (iter > 0) {
      float rs = 0.0f;
#pragma unroll
      for (int p = 0; p < PS; p++) rs += g_resacc[rp][p][bm];
      float res = rs * (1.0f / N_PTS);
      apply_update(Tm, bm, iter - 1, damping_prev, res);
      if (threadIdx.x < 16 && slice == 0)
        g_Tbuf[wq][(size_t)(b * M_HYP + m) * 16 + threadIdx.x] = Tm[threadIdx.x];
    }
  }

  float T00 = Tm[0], T01 = Tm[1], T02 = Tm[2],  T03 = Tm[3];
  float T10 = Tm[4], T11 = Tm[5], T12 = Tm[6],  T13 = Tm[7];
  float T20 = Tm[8], T21 = Tm[9], T22 = Tm[10], T23 = Tm[11];
  float fx = __ldg(Kin + b * 9 + 0) * scale, cx = __ldg(Kin + b * 9 + 2) * scale;
  float fy = __ldg(Kin + b * 9 + 4) * scale, cy = __ldg(Kin + b * 9 + 5) * scale;
  const __nv_bfloat16* Db = Dt + (size_t)b * H * W * C;
  const float* Ub = Umap + (size_t)b * H * W;
  const float* G  = geo + (size_t)b * N_PTS * 3;

  // ---- projection: lane l projects point slice*63 + w + 8*l ----
  float Wm1 = (float)(W - 1), Hm1 = (float)(H - 1);
  int nbeg = slice * 63 + w;
  int nend = min(N_PTS, slice * 63 + 63);
  int vc = (nend - nbeg + 7) >> 3;               // 1..8 points for this warp
  int n = min(nbeg + 8 * (lane & 7), N_PTS - 1);
  int o00, o01, o10, o11;
  float w00, w01, w10, w11, us;
  {
    float X = __ldg(G + n * 3 + 0);
    float Y = __ldg(G + n * 3 + 1);
    float Z = __ldg(G + n * 3 + 2);
    float px = T00 * X + T01 * Y + T02 * Z + T03;
    float py = T10 * X + T11 * Y + T12 * Z + T13;
    float pz = T20 * X + T21 * Y + T22 * Z + T23;
    float z  = fmaxf(pz, 1e-6f);
    float u  = fx * (px / z) + cx;
    float v  = fy * (py / z) + cy;
    float gx = 2.0f * u / Wm1 - 1.0f;
    float gy = 2.0f * v / Hm1 - 1.0f;
    float xs = fminf(fmaxf(((gx + 1.0f) * (float)W - 1.0f) * 0.5f, 0.0f), Wm1);
    float ys = fminf(fmaxf(((gy + 1.0f) * (float)H - 1.0f) * 0.5f, 0.0f), Hm1);
    float x0f = floorf(xs), y0f = floorf(ys);
    float x1f = fminf(x0f + 1.0f, Wm1), y1f = fminf(y0f + 1.0f, Hm1);
    float wx = xs - x0f, wy = ys - y0f;
    int x0 = (int)x0f, x1 = (int)x1f, y0 = (int)y0f, y1 = (int)y1f;
    w00 = (1.0f - wx) * (1.0f - wy); w01 = wx * (1.0f - wy);
    w10 = (1.0f - wx) * wy;          w11 = wx * wy;
    int r0 = y0 * W, r1 = y1 * W;
    us = w00 * __ldg(Ub + r0 + x0) + w01 * __ldg(Ub + r0 + x1)
       + w10 * __ldg(Ub + r1 + x0) + w11 * __ldg(Ub + r1 + x1);
    o00 = (r0 + x0) * 32; o01 = (r0 + x1) * 32;
    o10 = (r1 + x0) * 32; o11 = (r1 + x1) * 32;
  }

  float wacc = 0.0f;

  if constexpr (CPL == 4) {
    const uint2* base = (const uint2*)Db;
    uint2 ca, cb, cc2, cd;
    float cw00, cw01, cw10, cw11, cus;
    {
      int a00 = __shfl_sync(0xffffffffu, o00, 0), a01 = __shfl_sync(0xffffffffu, o01, 0);
      int a10 = __shfl_sync(0xffffffffu, o10, 0), a11 = __shfl_sync(0xffffffffu, o11, 0);
      cw00 = __shfl_sync(0xffffffffu, w00, 0); cw01 = __shfl_sync(0xffffffffu, w01, 0);
      cw10 = __shfl_sync(0xffffffffu, w10, 0); cw11 = __shfl_sync(0xffffffffu, w11, 0);
      cus  = __shfl_sync(0xffffffffu, us,  0);
      ca = __ldg(base + a00 + lane); cb = __ldg(base + a01 + lane);
      cc2 = __ldg(base + a10 + lane); cd = __ldg(base + a11 + lane);
    }
    for (int p = 0; p < vc; p++) {
      uint2 na = {}, nb = {}, nc = {}, nd = {};
      float nw00 = 0, nw01 = 0, nw10 = 0, nw11 = 0, nus = 0;
      if (p + 1 < vc) {
        int a00 = __shfl_sync(0xffffffffu, o00, p + 1), a01 = __shfl_sync(0xffffffffu, o01, p + 1);
        int a10 = __shfl_sync(0xffffffffu, o10, p + 1), a11 = __shfl_sync(0xffffffffu, o11, p + 1);
        nw00 = __shfl_sync(0xffffffffu, w00, p + 1); nw01 = __shfl_sync(0xffffffffu, w01, p + 1);
        nw10 = __shfl_sync(0xffffffffu, w10, p + 1); nw11 = __shfl_sync(0xffffffffu, w11, p + 1);
        nus  = __shfl_sync(0xffffffffu, us,  p + 1);
        na = __ldg(base + a00 + lane); nb = __ldg(base + a01 + lane);
        nc = __ldg(base + a10 + lane); nd = __ldg(base + a11 + lane);
      }
      float2 a0 = __bfloat1622float2(*(__nv_bfloat162*)&ca.x);
      float2 a1 = __bfloat1622float2(*(__nv_bfloat162*)&ca.y);
      float2 b0 = __bfloat1622float2(*(__nv_bfloat162*)&cb.x);
      float2 b1 = __bfloat1622float2(*(__nv_bfloat162*)&cb.y);
      float2 c0v = __bfloat1622float2(*(__nv_bfloat162*)&cc2.x);
      float2 c1 = __bfloat1622float2(*(__nv_bfloat162*)&cc2.y);
      float2 d0v = __bfloat1622float2(*(__nv_bfloat162*)&cd.x);
      float2 d1 = __bfloat1622float2(*(__nv_bfloat162*)&cd.y);
      float e0 = cw00 * a0.x; e0 = fmaf(cw01, b0.x, e0); e0 = fmaf(cw10, c0v.x, e0); e0 = fmaf(cw11, d0v.x, e0);
      float e1 = cw00 * a0.y; e1 = fmaf(cw01, b0.y, e1); e1 = fmaf(cw10, c0v.y, e1); e1 = fmaf(cw11, d0v.y, e1);
      float e2 = cw00 * a1.x; e2 = fmaf(cw01, b1.x, e2); e2 = fmaf(cw10, c1.x, e2); e2 = fmaf(cw11, d1.x, e2);
      float e3 = cw00 * a1.y; e3 = fmaf(cw01, b1.y, e3); e3 = fmaf(cw10, c1.y, e3); e3 = fmaf(cw11, d1.y, e3);
      float spt = e0 * e0 + e1 * e1 + e2 * e2 + e3 * e3;
      wacc = fmaf(cus, spt, wacc);
      ca = na; cb = nb; cc2 = nc; cd = nd;
      cw00 = nw00; cw01 = nw01; cw10 = nw10; cw11 = nw11; cus = nus;
    }
  } else if constexpr (CPL == 2) {
    const unsigned* base = (const unsigned*)Db;
    unsigned ca, cb, cc2, cd;
    float cw00, cw01, cw10, cw11, cus;
    {
      int a00 = __shfl_sync(0xffffffffu, o00, 0), a01 = __shfl_sync(0xffffffffu, o01, 0);
      int a10 = __shfl_sync(0xffffffffu, o10, 0), a11 = __shfl_sync(0xffffffffu, o11, 0);
      cw00 = __shfl_sync(0xffffffffu, w00, 0); cw01 = __shfl_sync(0xffffffffu, w01, 0);
      cw10 = __shfl_sync(0xffffffffu, w10, 0); cw11 = __shfl_sync(0xffffffffu, w11, 0);
      cus  = __shfl_sync(0xffffffffu, us,  0);
      ca = __ldg(base + a00 + lane); cb = __ldg(base + a01 + lane);
      cc2 = __ldg(base + a10 + lane); cd = __ldg(base + a11 + lane);
    }
    for (int p = 0; p < vc; p++) {
      unsigned na = 0, nb = 0, nc = 0, nd = 0;
      float nw00 = 0, nw01 = 0, nw10 = 0, nw11 = 0, nus = 0;
      if (p + 1 < vc) {
        int a00 = __shfl_sync(0xffffffffu, o00, p + 1), a01 = __shfl_sync(0xffffffffu, o01, p + 1);
        int a10 = __shfl_sync(0xffffffffu, o10, p + 1), a11 = __shfl_sync(0xffffffffu, o11, p + 1);
        nw00 = __shfl_sync(0xffffffffu, w00, p + 1); nw01 = __shfl_sync(0xffffffffu, w01, p + 1);
        nw10 = __shfl_sync(0xffffffffu, w10, p + 1); nw11 = __shfl_sync(0xffffffffu, w11, p + 1);
        nus  = __shfl_sync(0xffffffffu, us,  p + 1);
        na = __ldg(base + a00 + lane); nb = __ldg(base + a01 + lane);
        nc = __ldg(base + a10 + lane); nd = __ldg(base + a11 + lane);
      }
      float2 a = __bfloat1622float2(*(__nv_bfloat162*)&ca);
      float2 bq = __bfloat1622float2(*(__nv_bfloat162*)&cb);
      float2 c = __bfloat1622float2(*(__nv_bfloat162*)&cc2);
      float2 d = __bfloat1622float2(*(__nv_bfloat162*)&cd);
      float e0 = cw00 * a.x; e0 = fmaf(cw01, bq.x, e0); e0 = fmaf(cw10, c.x, e0); e0 = fmaf(cw11, d.x, e0);
      float e1 = cw00 * a.y; e1 = fmaf(cw01, bq.y, e1); e1 = fmaf(cw10, c.y, e1); e1 = fmaf(cw11, d.y, e1);
      float spt = e0 * e0 + e1 * e1;
      wacc = fmaf(cus, spt, wacc);
      ca = na; cb = nb; cc2 = nc; cd = nd;
      cw00 = nw00; cw01 = nw01; cw10 = nw10; cw11 = nw11; cus = nus;
    }
  } else {
    __nv_bfloat16 ca, cb, cc2, cd;
    float cw00, cw01, cw10, cw11, cus;
    {
      int a00 = __shfl_sync(0xffffffffu, o00, 0), a01 = __shfl_sync(0xffffffffu, o01, 0);
      int a10 = __shfl_sync(0xffffffffu, o10, 0), a11 = __shfl_sync(0xffffffffu, o11, 0);
      cw00 = __shfl_sync(0xffffffffu, w00, 0); cw01 = __shfl_sync(0xffffffffu, w01, 0);
      cw10 = __shfl_sync(0xffffffffu, w10, 0); cw11 = __shfl_sync(0xffffffffu, w11, 0);
      cus  = __shfl_sync(0xffffffffu, us,  0);
      ca = __ldg(Db + a00 + lane); cb = __ldg(Db + a01 + lane);
      cc2 = __ldg(Db + a10 + lane); cd = __ldg(Db + a11 + lane);
    }
    for (int p = 0; p < vc; p++) {
      __nv_bfloat16 na = __float2bfloat16(0.f), nb = na, nc = na, nd = na;
      float nw00 = 0, nw01 = 0, nw10 = 0, nw11 = 0, nus = 0;
      if (p + 1 < vc) {
        int a00 = __shfl_sync(0xffffffffu, o00, p + 1), a01 = __shfl_sync(0xffffffffu, o01, p + 1);
        int a10 = __shfl_sync(0xffffffffu, o10, p + 1), a11 = __shfl_sync(0xffffffffu, o11, p + 1);
        nw00 = __shfl_sync(0xffffffffu, w00, p + 1); nw01 = __shfl_sync(0xffffffffu, w01, p + 1);
        nw10 = __shfl_sync(0xffffffffu, w10, p + 1); nw11 = __shfl_sync(0xffffffffu, w11, p + 1);
        nus  = __shfl_sync(0xffffffffu, us,  p + 1);
        na = __ldg(Db + a00 + lane); nb = __ldg(Db + a01 + lane);
        nc = __ldg(Db + a10 + lane); nd = __ldg(Db + a11 + lane);
      }
      float e0 = cw00 * __bfloat162float(ca);
      e0 = fmaf(cw01, __bfloat162float(cb), e0);
      e0 = fmaf(cw10, __bfloat162float(cc2), e0);
      e0 = fmaf(cw11, __bfloat162float(cd), e0);
      float spt = e0 * e0;
      wacc = fmaf(cus, spt, wacc);
      ca = na; cb = nb; cc2 = nc; cd = nd;
      cw00 = nw00; cw01 = nw01; cw10 = nw10; cw11 = nw11; cus = nus;
    }
  }

#pragma unroll
  for (int o = 16; o; o >>= 1) wacc += __shfl_xor_sync(0xffffffffu, wacc, o);
  __shared__ float wpar[8];
  if (lane == 0) wpar[w] = wacc;
  __syncthreads();
  if (threadIdx.x == 0) {
    float s = 0.0f;
#pragma unroll
    for (int ww = 0; ww < 8; ww++) s += wpar[ww];
    g_resacc[wq][slice][bm] = s;
  }
}

// ---------------------------------------------------------------------------
// final kernel: applies the 9th LM update, then geodesic + argmin + output.
// ---------------------------------------------------------------------------
__global__ void final_kernel(const float* __restrict__ Tpred, float* __restrict__ out,
                             float damping_last)
{
  int b = blockIdx.x;
  int m = threadIdx.x;
  __shared__ float tot[M_HYP];
  if (m < M_HYP) {
    float Tc[16];
    const float* Tsrc = g_Tbuf[0] + (size_t)(b * M_HYP + m) * 16;
#pragma unroll
    for (int i = 0; i < 16; i++) Tc[i] = Tsrc[i];
    float c = 0.0f;
    if (m < M16) {
      int bm = b * M16 + m;
      float rs = 0.0f;
#pragma unroll
      for (int p = 0; p < PS; p++) rs += g_resacc[0][p][bm];
      c = rs * (1.0f / N_PTS);
      apply_update(Tc, bm, 8, damping_last, c);
    }
    const float* P = Tpred + b * 16;
    float Ri[9] = { P[0], P[4], P[8],  P[1], P[5], P[9],  P[2], P[6], P[10] };
    float tix = -(Ri[0] * P[3] + Ri[1] * P[7] + Ri[2] * P[11]);
    float tiy = -(Ri[3] * P[3] + Ri[4] * P[7] + Ri[5] * P[11]);
    float tiz = -(Ri[6] * P[3] + Ri[7] * P[7] + Ri[8] * P[11]);
    float Ti[16] = { Ri[0], Ri[1], Ri[2], tix,
                     Ri[3], Ri[4], Ri[5], tiy,
                     Ri[6], Ri[7], Ri[8], tiz,
                     0.f, 0.f, 0.f, 1.f };
    float A[16];
#pragma unroll
    for (int i = 0; i < 4; i++)
#pragma unroll
      for (int j = 0; j < 4; j++)
        A[i * 4 + j] = Tc[i * 4 + 0] * Ti[0 * 4 + j] + Tc[i * 4 + 1] * Ti[1 * 4 + j]
                     + Tc[i * 4 + 2] * Ti[2 * 4 + j] + Tc[i * 4 + 3] * Ti[3 * 4 + j];
    float cos_a = (A[0] + A[5] + A[10] - 1.0f) * 0.5f;
    const float CL = (float)(1.0 - 1e-7);
    cos_a = fminf(fmaxf(cos_a, -CL), CL);
    float theta = acosf(cos_a);
    float th = fmaxf(theta, 1e-8f);
    float sn = fmaxf(sinf(th), 1e-8f);
    float wx = (A[9] - A[6]) / (2.0f * sn) * th;
    float wy = (A[2] - A[8]) / (2.0f * sn) * th;
    float wz = (A[4] - A[1]) / (2.0f * sn) * th;
    if (fabsf(theta) < 1e-6f) { wx = 0.f; wy = 0.f; wz = 0.f; }
    float tx = A[3], ty = A[7], tz = A[11];
    float geod = sqrtf(tx * tx + ty * ty + tz * tz + wx * wx + wy * wy + wz * wz);
    tot[m] = c + geod;
    out[128 + b * M_HYP + m] = c;
    float* Tdst = g_Tbuf[1] + (size_t)(b * M_HYP + m) * 16;
#pragma unroll
    for (int i = 0; i < 16; i++) Tdst[i] = Tc[i];
  }
  __syncthreads();
  if (m == 0) {
    int best = 0;
    float bv = tot[0];
    for (int i = 1; i < M_HYP; i++)
      if (tot[i] < bv) { bv = tot[i]; best = i; }
    const float* Tb = g_Tbuf[1] + (size_t)(b * M_HYP + best) * 16;
#pragma unroll
    for (int i = 0; i < 16; i++) out[b * 16 + i] = Tb[i];
  }
}

// ---------------------------------------------------------------------------
// Host launch
// ---------------------------------------------------------------------------
extern "C" void kernel_launch(void* const* d_in, const int* in_sizes, int n_in,
                              void* d_out, int out_size)
{
  const float* T_pred = (const float*)d_in[0];
  const float* geo    = (const float*)d_in[1];
  const float* Kin    = (const float*)d_in[2];
  const float* q0 = (const float*)d_in[3];
  const float* q1 = (const float*)d_in[4];
  const float* q2 = (const float*)d_in[5];
  const float* r0 = (const float*)d_in[6];
  const float* r1 = (const float*)d_in[7];
  const float* r2 = (const float*)d_in[8];
  const float* u0 = (const float*)d_in[9];
  const float* u1 = (const float*)d_in[10];
  const float* u2 = (const float*)d_in[11];
  float* out = (float*)d_out;

  __nv_bfloat16 *D0p, *D1p, *D2p;
  cudaGetSymbolAddress((void**)&D0p, g_D0);
  cudaGetSymbolAddress((void**)&D1p, g_D1);
  cudaGetSymbolAddress((void**)&D2p, g_D2);

  // side stream (LOW priority) + events, created once on the uncaptured call
  static cudaStream_t s2 = nullptr;
  static cudaEvent_t evFork = nullptr, evJoin = nullptr;
  static bool tried = false;
  if (!tried) {
    tried = true;
    int loPri = 0, hiPri = 0;
    cudaDeviceGetStreamPriorityRange(&loPri, &hiPri);   // loPri = numerically largest
    if (cudaStreamCreateWithPriority(&s2, cudaStreamNonBlocking, loPri) != cudaSuccess)
      s2 = nullptr;
    if (cudaEventCreateWithFlags(&evFork, cudaEventDisableTiming) != cudaSuccess) evFork = nullptr;
    if (cudaEventCreateWithFlags(&evJoin, cudaEventDisableTiming) != cudaSuccess) evJoin = nullptr;
  }
  bool use2 = (s2 && evFork && evJoin);

  unsigned hk0, hk1;
  threefry2x32(0u, 42u, 0u, 0u, &hk0, &hk1);

  // prep A (hyp + noise + L0) FIRST on main stream — it gates iteration 0.
  // prep B (L1+L2) forked onto the low-priority side stream afterwards.
  if (use2) {
    cudaEventRecord(evFork, 0);                    // fork point: before prep_A
    prep_kernel_A<<<B_SZ + 1 + T0_TILES, 256>>>(q0, r0, D0p, T_pred, hk0, hk1);
    cudaStreamWaitEvent(s2, evFork, 0);
    prep_kernel_B<<<T1_TILES + T2_TILES, 256, 0, s2>>>(q1, r1, q2, r2, D1p, D2p);
    cudaEventRecord(evJoin, s2);
  } else {
    prep_kernel_A<<<B_SZ + 1 + T0_TILES, 256>>>(q0, r0, D0p, T_pred, hk0, hk1);
    prep_kernel_B<<<T1_TILES + T2_TILES, 256>>>(q1, r1, q2, r2, D1p, D2p);
  }

  const int   lvl[N_ITER]  = {0, 0, 1, 1, 1, 2, 2, 2, 2};
  const float damp[3]      = {0.001f, 0.0005f, 0.00025f};
  const int   grid_res = B_SZ * M16 * PS;    // 1024 blocks
  for (int k = 0; k < N_ITER; k++) {
    int level = lvl[k];
    if (k == 2 && use2) cudaStreamWaitEvent(0, evJoin, 0);   // join before L1 use
    float scale = 1.0f / (4.0f / (float)(1 << level));
    float dprev = (k > 0) ? damp[lvl[k - 1]] : 0.0f;
    if (level == 0)
      residual_kernel<4><<<grid_res, 256>>>(D0p, u0, geo, Kin, C0, H0, W0, scale, k, dprev);
    else if (level == 1)
      residual_kernel<2><<<grid_res, 256>>>(D1p, u1, geo, Kin, C1, H1, W1, scale, k, dprev);
    else
      residual_kernel<1><<<grid_res, 256>>>(D2p, u2, geo, Kin, C2, H2, W2, scale, k, dprev);
  }

  final_kernel<<<B_SZ, M_HYP>>>(T_pred, out, damp[2]);
  (void)in_sizes; (void)n_in; (void)out_size;
}

// round 16
// speedup vs baseline: 1.1699x; 1.0692x over previous
#include <cuda_runtime.h>
#include <cuda_bf16.h>
#include <math.h>

// ---------------------------------------------------------------------------
// Problem dimensions (fixed by the reference setup)
// ---------------------------------------------------------------------------
#define B_SZ   8
#define N_PTS  500
#define M_HYP  144
#define M16    16
#define PS     8           // point slices per (b,m): 63 points each (last: 59)
#define N_ITER 9

#define C0 128
#define H0 48
#define W0 64
#define C1 64
#define H1 96
#define W1 128
#define C2 32
#define H2 192
#define W2 256

// transpose tile counts (32x32 tiles)
#define T0_TILES ((H0*W0/32) * (C0/32) * B_SZ)   // 3072
#define T1_TILES ((H1*W1/32) * (C1/32) * B_SZ)   // 6144
#define T2_TILES ((H2*W2/32) * (C2/32) * B_SZ)   // 12288

// ---------------------------------------------------------------------------
// Scratch (__device__ globals — no allocation allowed). D stored as bf16
// (bf16 halves prefetch register footprint; occupancy wins — round 14).
// ---------------------------------------------------------------------------
__device__ __nv_bfloat16 g_D0[(size_t)B_SZ * H0 * W0 * C0];   // q0-r0, channel-last
__device__ __nv_bfloat16 g_D1[(size_t)B_SZ * H1 * W1 * C1];
__device__ __nv_bfloat16 g_D2[(size_t)B_SZ * H2 * W2 * C2];
__device__ float g_Tbuf[2][B_SZ * M_HYP * 16];       // double-buffered poses
__device__ float g_resacc[2][PS][B_SZ * M16];         // double-buffered partial residuals
__device__ float g_noise[N_ITER * B_SZ * M16 * 6];    // precomputed LM noise (m<16 only)

// ---------------------------------------------------------------------------
// Threefry-2x32 (exactly JAX's 20-round schedule; KAT-verified)
// ---------------------------------------------------------------------------
__host__ __device__ __forceinline__ void threefry2x32(
    unsigned k0, unsigned k1, unsigned x0, unsigned x1,
    unsigned* o0, unsigned* o1)
{
  unsigned ks2 = k0 ^ k1 ^ 0x1BD11BDAu;
#define TFR(r) { x0 += x1; x1 = (x1 << (r)) | (x1 >> (32 - (r))); x1 ^= x0; }
  x0 += k0;  x1 += k1;
  TFR(13) TFR(15) TFR(26) TFR(6)
  x0 += k1;  x1 += ks2 + 1u;
  TFR(17) TFR(29) TFR(16) TFR(24)
  x0 += ks2; x1 += k0 + 2u;
  TFR(13) TFR(15) TFR(26) TFR(6)
  x0 += k0;  x1 += k1 + 3u;
  TFR(17) TFR(29) TFR(16) TFR(24)
  x0 += k1;  x1 += ks2 + 4u;
  TFR(13) TFR(15) TFR(26) TFR(6)
  x0 += ks2; x1 += k0 + 5u;
#undef TFR
  *o0 = x0; *o1 = x1;
}

// Giles/XLA erfinv (same coefficients as XLA ErfInv32)
__device__ __forceinline__ float erfinv_f(float x)
{
  float w = -log1pf(-x * x);
  float p;
  if (w < 5.0f) {
    w = w - 2.5f;
    p = 2.81022636e-08f;
    p = fmaf(p, w, 3.43273939e-07f);
    p = fmaf(p, w, -3.5233877e-06f);
    p = fmaf(p, w, -4.39150654e-06f);
    p = fmaf(p, w, 0.00021858087f);
    p = fmaf(p, w, -0.00125372503f);
    p = fmaf(p, w, -0.00417768164f);
    p = fmaf(p, w, 0.246640727f);
    p = fmaf(p, w, 1.50140941f);
  } else {
    w = sqrtf(w) - 3.0f;
    p = -0.000200214257f;
    p = fmaf(p, w, 0.000100950558f);
    p = fmaf(p, w, 0.00134934322f);
    p = fmaf(p, w, -0.00367342844f);
    p = fmaf(p, w, 0.00573950773f);
    p = fmaf(p, w, -0.0076224613f);
    p = fmaf(p, w, 0.00943887047f);
    p = fmaf(p, w, 1.00167406f);
    p = fmaf(p, w, 2.83297682f);
  }
  return p * x;
}

__device__ __forceinline__ float bits_to_normal(unsigned bits)
{
  float u = __uint_as_float((bits >> 9) | 0x3f800000u) - 1.0f;
  const float lo = -0.99999994f;
  float v = fmaxf(lo, u * 2.0f + lo);
  return 1.41421356237f * erfinv_f(v);
}

// PARTITIONABLE threefry: (y0,y1) = threefry(key; 0, j); 32-bit draw = y0 ^ y1.
__device__ __forceinline__ float jax_normal_elem(unsigned k0, unsigned k1, unsigned j)
{
  unsigned y0, y1;
  threefry2x32(k0, k1, 0u, j, &y0, &y1);
  return bits_to_normal(y0 ^ y1);
}

// ---------------------------------------------------------------------------
// se3_exp (matches reference element-by-element)
// ---------------------------------------------------------------------------
__device__ __forceinline__ void mat3mul(const float* A, const float* Bm, float* Cm)
{
#pragma unroll
  for (int i = 0; i < 3; i++)
#pragma unroll
    for (int j = 0; j < 3; j++)
      Cm[i * 3 + j] = A[i * 3 + 0] * Bm[0 * 3 + j] + A[i * 3 + 1] * Bm[1 * 3 + j] + A[i * 3 + 2] * Bm[2 * 3 + j];
}

__device__ void se3_exp6(const float xi[6], float T[16])
{
  float tx = xi[0], ty = xi[1], tz = xi[2];
  float wx = xi[3], wy = xi[4], wz = xi[5];
  float theta = fmaxf(sqrtf(wx * wx + wy * wy + wz * wz), 1e-8f);
  float kx = wx / theta, ky = wy / theta, kz = wz / theta;
  float K[9] = { 0.f, -kz, ky,  kz, 0.f, -kx,  -ky, kx, 0.f };
  float KK[9];
  mat3mul(K, K, KK);
  float st = sinf(theta);
  float ct = 1.0f - cosf(theta);
  float a  = ct / theta;
  float bb = 1.0f - st / theta;
  float R[9], V[9];
#pragma unroll
  for (int i = 0; i < 9; i++) {
    float e = (i == 0 || i == 4 || i == 8) ? 1.0f : 0.0f;
    R[i] = e + st * K[i] + ct * KK[i];
    V[i] = e + a  * K[i] + bb * KK[i];
  }
  float tox = V[0] * tx + V[1] * ty + V[2] * tz;
  float toy = V[3] * tx + V[4] * ty + V[5] * tz;
  float toz = V[6] * tx + V[7] * ty + V[8] * tz;
  T[0] = R[0]; T[1] = R[1]; T[2]  = R[2]; T[3]  = tox;
  T[4] = R[3]; T[5] = R[4]; T[6]  = R[5]; T[7]  = toy;
  T[8] = R[6]; T[9] = R[7]; T[10] = R[8]; T[11] = toz;
  T[12] = 0.f; T[13] = 0.f; T[14] = 0.f; T[15] = 1.f;
}

// Apply LM delta for item bm (= b*16+m): T_out = se3_exp(step) @ T_in
__device__ __forceinline__ void apply_update(
    float Tm[16], int bm, int noise_iter, float damping, float res)
{
  const float* nz = g_noise + ((size_t)(noise_iter * (B_SZ * M16) + bm)) * 6;
  float s1 = -damping * res * 0.01f;
  float xi[6];
#pragma unroll
  for (int k = 0; k < 6; k++) xi[k] = s1 * nz[k];
  float D[16];
  se3_exp6(xi, D);
  float Told[16];
#pragma unroll
  for (int t = 0; t < 16; t++) Told[t] = Tm[t];
#pragma unroll
  for (int r = 0; r < 4; r++)
#pragma unroll
    for (int cc = 0; cc < 4; cc++)
      Tm[r * 4 + cc] = D[r * 4 + 0] * Told[0 * 4 + cc] + D[r * 4 + 1] * Told[1 * 4 + cc]
                     + D[r * 4 + 2] * Told[2 * 4 + cc] + D[r * 4 + 3] * Told[3 * 4 + cc];
}

// ---------------------------------------------------------------------------
// Transpose helper: one 32x32 tile of D = q - r, (B,C,HW) -> (B,HW,C), bf16
// ---------------------------------------------------------------------------
__device__ __forceinline__ void do_tile(
    const float* __restrict__ q, const float* __restrict__ r,
    __nv_bfloat16* __restrict__ Dt, int C, int HW,
    int b, int c0, int hw0, float* tile /* [32][33] */)
{
  const float* qb = q + (size_t)b * C * HW;
  const float* rb = r + (size_t)b * C * HW;
  __nv_bfloat16* Db = Dt + (size_t)b * HW * C;
  int tx = threadIdx.x & 31, ty = threadIdx.x >> 5;
#pragma unroll
  for (int i = ty; i < 32; i += 8) {
    int c = c0 + i, hw = hw0 + tx;
    tile[i * 33 + tx] = qb[(size_t)c * HW + hw] - rb[(size_t)c * HW + hw];
  }
  __syncthreads();
  int tid = threadIdx.x;
#pragma unroll
  for (int idx = tid; idx < 32 * 16; idx += 256) {
    int row = idx >> 4;
    int pr  = idx & 15;
    __nv_bfloat162 h = __floats2bfloat162_rn(tile[(2 * pr) * 33 + row],
                                             tile[(2 * pr + 1) * 33 + row]);
    *(__nv_bfloat162*)(Db + (size_t)(hw0 + row) * C + c0 + 2 * pr) = h;
  }
}

// ---------------------------------------------------------------------------
// prep A: blocks [0,8) = hypotheses; block 8 = noise; rest = L0 tiles
// ---------------------------------------------------------------------------
__global__ __launch_bounds__(256) void prep_kernel_A(
    const float* __restrict__ q0, const float* __restrict__ r0,
    __nv_bfloat16* __restrict__ D0,
    const float* __restrict__ Tpred, unsigned k0, unsigned k1)
{
  __shared__ float tile[32 * 33];
  int blk = blockIdx.x;
  if (blk < B_SZ) {
    int m = threadIdx.x;
    int b = blk;
    if (m >= M_HYP) return;
    float xi[6];
#pragma unroll
    for (int k = 0; k < 3; k++)
      xi[k] = jax_normal_elem(k0, k1, (unsigned)(m * 3 + k));
    int pi = m / 12, yj = m % 12;
    const float D2R = (float)(3.14159265358979323846 / 180.0);
    xi[3] = 0.0f;
    xi[4] = (-11.0f + 2.0f * (float)pi) * D2R;
    xi[5] = (-11.0f + 2.0f * (float)yj) * D2R;
    float dT[16];
    se3_exp6(xi, dT);
    const float* P = Tpred + b * 16;
    size_t off = (size_t)(b * M_HYP + m) * 16;
#pragma unroll
    for (int i = 0; i < 4; i++)
#pragma unroll
      for (int j = 0; j < 4; j++) {
        float v = dT[i * 4 + 0] * P[0 * 4 + j] + dT[i * 4 + 1] * P[1 * 4 + j]
                + dT[i * 4 + 2] * P[2 * 4 + j] + dT[i * 4 + 3] * P[3 * 4 + j];
        g_Tbuf[0][off + i * 4 + j] = v;
        g_Tbuf[1][off + i * 4 + j] = v;
      }
    return;
  }
  blk -= B_SZ;
  if (blk == 0) {
    const int LI[N_ITER] = {100, 101, 110, 111, 112, 120, 121, 122, 123};
    int tid = threadIdx.x;
    for (int it = 0; it < N_ITER; it++) {
      unsigned ik0, ik1;
      threefry2x32(0u, 42u, 0u, (unsigned)LI[it], &ik0, &ik1);
      for (int idx = tid; idx < B_SZ * M16 * 6; idx += 256) {
        int i = idx / 6, k = idx % 6;
        int b = i >> 4, m = i & 15;
        unsigned j = (unsigned)((b * M_HYP + m) * 6 + k);
        g_noise[it * (B_SZ * M16 * 6) + idx] = jax_normal_elem(ik0, ik1, j);
      }
    }
    return;
  }
  blk -= 1;
  {
    const int HWT = H0 * W0 / 32, CT = C0 / 32;
    int b = blk / (HWT * CT);
    int rem = blk % (HWT * CT);
    int c0 = (rem / HWT) * 32, hw0 = (rem % HWT) * 32;
    do_tile(q0, r0, D0, C0, H0 * W0, b, c0, hw0, tile);
  }
}

// ---------------------------------------------------------------------------
// prep B: L1 + L2 tiles (overlapped with the two L0 residual iterations)
// ---------------------------------------------------------------------------
__global__ __launch_bounds__(256) void prep_kernel_B(
    const float* __restrict__ q1, const float* __restrict__ r1,
    const float* __restrict__ q2, const float* __restrict__ r2,
    __nv_bfloat16* __restrict__ D1, __nv_bfloat16* __restrict__ D2)
{
  __shared__ float tile[32 * 33];
  int blk = blockIdx.x;
  if (blk < T1_TILES) {
    const int HWT = H1 * W1 / 32, CT = C1 / 32;
    int b = blk / (HWT * CT);
    int rem = blk % (HWT * CT);
    int c0 = (rem / HWT) * 32, hw0 = (rem % HWT) * 32;
    do_tile(q1, r1, D1, C1, H1 * W1, b, c0, hw0, tile);
    return;
  }
  blk -= T1_TILES;
  {
    const int HWT = H2 * W2 / 32;
    int b = blk / HWT;
    int hw0 = (blk % HWT) * 32;
    do_tile(q2, r2, D2, C2, H2 * W2, b, 0, hw0, tile);
  }
}

// ---------------------------------------------------------------------------
// Residual kernel. grid = B*16*PS = 1024 blocks, 256 threads (8 warps).
// LM-update prologue runs in WARP 0 ONLY (saves ~7/8 of prologue issue slots);
// Tm broadcast via shared memory. Tm-independent loads (geo point) hoisted
// above the barrier so waiting warps have loads in flight.
// Warp w owns points n = slice*63 + w + 8*p (p = 0..vc-1, vc <= 8).
// Lane l (l<8) projects point p=l; channel loop broadcasts each point with
// a 1-deep software prefetch pipeline.
// ---------------------------------------------------------------------------
template <int CPL>
__global__ __launch_bounds__(256) void residual_kernel(
    const __nv_bfloat16* __restrict__ Dt, const float* __restrict__ Umap,
    const float* __restrict__ geo, const float* __restrict__ Kin,
    int C, int H, int W, float scale, int iter, float damping_prev)
{
  int bm    = blockIdx.x >> 3;
  int slice = blockIdx.x & 7;
  int b = bm >> 4, m = bm & 15;
  int lane = threadIdx.x & 31, w = threadIdx.x >> 5;
  int rp = (iter + 1) & 1, wq = iter & 1;

  const __nv_bfloat16* Db = Dt + (size_t)b * H * W * C;
  const float* Ub = Umap + (size_t)b * H * W;
  const float* G  = geo + (size_t)b * N_PTS * 3;

  // ---- Tm-independent loads first (in flight during warp-0 prologue) ----
  int nbeg = slice * 63 + w;
  int nend = min(N_PTS, slice * 63 + 63);
  int vc = (nend - nbeg + 7) >> 3;               // 1..8 points for this warp
  int n = min(nbeg + 8 * (lane & 7), N_PTS - 1);
  float X = __ldg(G + n * 3 + 0);
  float Y = __ldg(G + n * 3 + 1);
  float Z = __ldg(G + n * 3 + 2);
  float fx = __ldg(Kin + b * 9 + 0) * scale, cx = __ldg(Kin + b * 9 + 2) * scale;
  float fy = __ldg(Kin + b * 9 + 4) * scale, cy = __ldg(Kin + b * 9 + 5) * scale;

  // ---- prologue: WARP 0 computes T_iter; broadcast via shared ----
  __shared__ float sT[16];
  if (w == 0) {
    float Tm[16];
    const float* Tsrc = g_Tbuf[rp] + (size_t)(b * M_HYP + m) * 16;
#pragma unroll
    for (int i = 0; i < 16; i++) Tm[i] = Tsrc[i];
    if (iter > 0) {
      float rs = 0.0f;
#pragma unroll
      for (int p = 0; p < PS; p++) rs += g_resacc[rp][p][bm];
      float res = rs * (1.0f / N_PTS);
      apply_update(Tm, bm, iter - 1, damping_prev, res);
      if (slice == 0 && lane < 16)
        g_Tbuf[wq][(size_t)(b * M_HYP + m) * 16 + lane] = Tm[lane];
    }
    if (lane < 16) sT[lane] = Tm[lane];
  }
  __syncthreads();

  float T00 = sT[0], T01 = sT[1], T02 = sT[2],  T03 = sT[3];
  float T10 = sT[4], T11 = sT[5], T12 = sT[6],  T13 = sT[7];
  float T20 = sT[8], T21 = sT[9], T22 = sT[10], T23 = sT[11];

  // ---- projection: lane l projects point slice*63 + w + 8*l ----
  float Wm1 = (float)(W - 1), Hm1 = (float)(H - 1);
  int o00, o01, o10, o11;
  float w00, w01, w10, w11, us;
  {
    float px = T00 * X + T01 * Y + T02 * Z + T03;
    float py = T10 * X + T11 * Y + T12 * Z + T13;
    float pz = T20 * X + T21 * Y + T22 * Z + T23;
    float z  = fmaxf(pz, 1e-6f);
    float u  = fx * (px / z) + cx;
    float v  = fy * (py / z) + cy;
    float gx = 2.0f * u / Wm1 - 1.0f;
    float gy = 2.0f * v / Hm1 - 1.0f;
    float xs = fminf(fmaxf(((gx + 1.0f) * (float)W - 1.0f) * 0.5f, 0.0f), Wm1);
    float ys = fminf(fmaxf(((gy + 1.0f) * (float)H - 1.0f) * 0.5f, 0.0f), Hm1);
    float x0f = floorf(xs), y0f = floorf(ys);
    float x1f = fminf(x0f + 1.0f, Wm1), y1f = fminf(y0f + 1.0f, Hm1);
    float wx = xs - x0f, wy = ys - y0f;
    int x0 = (int)x0f, x1 = (int)x1f, y0 = (int)y0f, y1 = (int)y1f;
    w00 = (1.0f - wx) * (1.0f - wy); w01 = wx * (1.0f - wy);
    w10 = (1.0f - wx) * wy;          w11 = wx * wy;
    int r0 = y0 * W, r1 = y1 * W;
    us = w00 * __ldg(Ub + r0 + x0) + w01 * __ldg(Ub + r0 + x1)
       + w10 * __ldg(Ub + r1 + x0) + w11 * __ldg(Ub + r1 + x1);
    o00 = (r0 + x0) * 32; o01 = (r0 + x1) * 32;
    o10 = (r1 + x0) * 32; o11 = (r1 + x1) * 32;
  }

  float wacc = 0.0f;

  if constexpr (CPL == 4) {
    const uint2* base = (const uint2*)Db;
    uint2 ca, cb, cc2, cd;
    float cw00, cw01, cw10, cw11, cus;
    {
      int a00 = __shfl_sync(0xffffffffu, o00, 0), a01 = __shfl_sync(0xffffffffu, o01, 0);
      int a10 = __shfl_sync(0xffffffffu, o10, 0), a11 = __shfl_sync(0xffffffffu, o11, 0);
      cw00 = __shfl_sync(0xffffffffu, w00, 0); cw01 = __shfl_sync(0xffffffffu, w01, 0);
      cw10 = __shfl_sync(0xffffffffu, w10, 0); cw11 = __shfl_sync(0xffffffffu, w11, 0);
      cus  = __shfl_sync(0xffffffffu, us,  0);
      ca = __ldg(base + a00 + lane); cb = __ldg(base + a01 + lane);
      cc2 = __ldg(base + a10 + lane); cd = __ldg(base + a11 + lane);
    }
    for (int p = 0; p < vc; p++) {
      uint2 na = {}, nb = {}, nc = {}, nd = {};
      float nw00 = 0, nw01 = 0, nw10 = 0, nw11 = 0, nus = 0;
      if (p + 1 < vc) {
        int a00 = __shfl_sync(0xffffffffu, o00, p + 1), a01 = __shfl_sync(0xffffffffu, o01, p + 1);
        int a10 = __shfl_sync(0xffffffffu, o10, p + 1), a11 = __shfl_sync(0xffffffffu, o11, p + 1);
        nw00 = __shfl_sync(0xffffffffu, w00, p + 1); nw01 = __shfl_sync(0xffffffffu, w01, p + 1);
        nw10 = __shfl_sync(0xffffffffu, w10, p + 1); nw11 = __shfl_sync(0xffffffffu, w11, p + 1);
        nus  = __shfl_sync(0xffffffffu, us,  p + 1);
        na = __ldg(base + a00 + lane); nb = __ldg(base + a01 + lane);
        nc = __ldg(base + a10 + lane); nd = __ldg(base + a11 + lane);
      }
      float2 a0 = __bfloat1622float2(*(__nv_bfloat162*)&ca.x);
      float2 a1 = __bfloat1622float2(*(__nv_bfloat162*)&ca.y);
      float2 b0 = __bfloat1622float2(*(__nv_bfloat162*)&cb.x);
      float2 b1 = __bfloat1622float2(*(__nv_bfloat162*)&cb.y);
      float2 c0v = __bfloat1622float2(*(__nv_bfloat162*)&cc2.x);
      float2 c1 = __bfloat1622float2(*(__nv_bfloat162*)&cc2.y);
      float2 d0v = __bfloat1622float2(*(__nv_bfloat162*)&cd.x);
      float2 d1 = __bfloat1622float2(*(__nv_bfloat162*)&cd.y);
      float e0 = cw00 * a0.x; e0 = fmaf(cw01, b0.x, e0); e0 = fmaf(cw10, c0v.x, e0); e0 = fmaf(cw11, d0v.x, e0);
      float e1 = cw00 * a0.y; e1 = fmaf(cw01, b0.y, e1); e1 = fmaf(cw10, c0v.y, e1); e1 = fmaf(cw11, d0v.y, e1);
      float e2 = cw00 * a1.x; e2 = fmaf(cw01, b1.x, e2); e2 = fmaf(cw10, c1.x, e2); e2 = fmaf(cw11, d1.x, e2);
      float e3 = cw00 * a1.y; e3 = fmaf(cw01, b1.y, e3); e3 = fmaf(cw10, c1.y, e3); e3 = fmaf(cw11, d1.y, e3);
      float spt = e0 * e0 + e1 * e1 + e2 * e2 + e3 * e3;
      wacc = fmaf(cus, spt, wacc);
      ca = na; cb = nb; cc2 = nc; cd = nd;
      cw00 = nw00; cw01 = nw01; cw10 = nw10; cw11 = nw11; cus = nus;
    }
  } else if constexpr (CPL == 2) {
    const unsigned* base = (const unsigned*)Db;
    unsigned ca, cb, cc2, cd;
    float cw00, cw01, cw10, cw11, cus;
    {
      int a00 = __shfl_sync(0xffffffffu, o00, 0), a01 = __shfl_sync(0xffffffffu, o01, 0);
      int a10 = __shfl_sync(0xffffffffu, o10, 0), a11 = __shfl_sync(0xffffffffu, o11, 0);
      cw00 = __shfl_sync(0xffffffffu, w00, 0); cw01 = __shfl_sync(0xffffffffu, w01, 0);
      cw10 = __shfl_sync(0xffffffffu, w10, 0); cw11 = __shfl_sync(0xffffffffu, w11, 0);
      cus  = __shfl_sync(0xffffffffu, us,  0);
      ca = __ldg(base + a00 + lane); cb = __ldg(base + a01 + lane);
      cc2 = __ldg(base + a10 + lane); cd = __ldg(base + a11 + lane);
    }
    for (int p = 0; p < vc; p++) {
      unsigned na = 0, nb = 0, nc = 0, nd = 0;
      float nw00 = 0, nw01 = 0, nw10 = 0, nw11 = 0, nus = 0;
      if (p + 1 < vc) {
        int a00 = __shfl_sync(0xffffffffu, o00, p + 1), a01 = __shfl_sync(0xffffffffu, o01, p + 1);
        int a10 = __shfl_sync(0xffffffffu, o10, p + 1), a11 = __shfl_sync(0xffffffffu, o11, p + 1);
        nw00 = __shfl_sync(0xffffffffu, w00, p + 1); nw01 = __shfl_sync(0xffffffffu, w01, p + 1);
        nw10 = __shfl_sync(0xffffffffu, w10, p + 1); nw11 = __shfl_sync(0xffffffffu, w11, p + 1);
        nus  = __shfl_sync(0xffffffffu, us,  p + 1);
        na = __ldg(base + a00 + lane); nb = __ldg(base + a01 + lane);
        nc = __ldg(base + a10 + lane); nd = __ldg(base + a11 + lane);
      }
      float2 a = __bfloat1622float2(*(__nv_bfloat162*)&ca);
      float2 bq = __bfloat1622float2(*(__nv_bfloat162*)&cb);
      float2 c = __bfloat1622float2(*(__nv_bfloat162*)&cc2);
      float2 d = __bfloat1622float2(*(__nv_bfloat162*)&cd);
      float e0 = cw00 * a.x; e0 = fmaf(cw01, bq.x, e0); e0 = fmaf(cw10, c.x, e0); e0 = fmaf(cw11, d.x, e0);
      float e1 = cw00 * a.y; e1 = fmaf(cw01, bq.y, e1); e1 = fmaf(cw10, c.y, e1); e1 = fmaf(cw11, d.y, e1);
      float spt = e0 * e0 + e1 * e1;
      wacc = fmaf(cus, spt, wacc);
      ca = na; cb = nb; cc2 = nc; cd = nd;
      cw00 = nw00; cw01 = nw01; cw10 = nw10; cw11 = nw11; cus = nus;
    }
  } else {
    __nv_bfloat16 ca, cb, cc2, cd;
    float cw00, cw01, cw10, cw11, cus;
    {
      int a00 = __shfl_sync(0xffffffffu, o00, 0), a01 = __shfl_sync(0xffffffffu, o01, 0);
      int a10 = __shfl_sync(0xffffffffu, o10, 0), a11 = __shfl_sync(0xffffffffu, o11, 0);
      cw00 = __shfl_sync(0xffffffffu, w00, 0); cw01 = __shfl_sync(0xffffffffu, w01, 0);
      cw10 = __shfl_sync(0xffffffffu, w10, 0); cw11 = __shfl_sync(0xffffffffu, w11, 0);
      cus  = __shfl_sync(0xffffffffu, us,  0);
      ca = __ldg(Db + a00 + lane); cb = __ldg(Db + a01 + lane);
      cc2 = __ldg(Db + a10 + lane); cd = __ldg(Db + a11 + lane);
    }
    for (int p = 0; p < vc; p++) {
      __nv_bfloat16 na = __float2bfloat16(0.f), nb = na, nc = na, nd = na;
      float nw00 = 0, nw01 = 0, nw10 = 0, nw11 = 0, nus = 0;
      if (p + 1 < vc) {
        int a00 = __shfl_sync(0xffffffffu, o00, p + 1), a01 = __shfl_sync(0xffffffffu, o01, p + 1);
        int a10 = __shfl_sync(0xffffffffu, o10, p + 1), a11 = __shfl_sync(0xffffffffu, o11, p + 1);
        nw00 = __shfl_sync(0xffffffffu, w00, p + 1); nw01 = __shfl_sync(0xffffffffu, w01, p + 1);
        nw10 = __shfl_sync(0xffffffffu, w10, p + 1); nw11 = __shfl_sync(0xffffffffu, w11, p + 1);
        nus  = __shfl_sync(0xffffffffu, us,  p + 1);
        na = __ldg(Db + a00 + lane); nb = __ldg(Db + a01 + lane);
        nc = __ldg(Db + a10 + lane); nd = __ldg(Db + a11 + lane);
      }
      float e0 = cw00 * __bfloat162float(ca);
      e0 = fmaf(cw01, __bfloat162float(cb), e0);
      e0 = fmaf(cw10, __bfloat162float(cc2), e0);
      e0 = fmaf(cw11, __bfloat162float(cd), e0);
      float spt = e0 * e0;
      wacc = fmaf(cus, spt, wacc);
      ca = na; cb = nb; cc2 = nc; cd = nd;
      cw00 = nw00; cw01 = nw01; cw10 = nw10; cw11 = nw11; cus = nus;
    }
  }

#pragma unroll
  for (int o = 16; o; o >>= 1) wacc += __shfl_xor_sync(0xffffffffu, wacc, o);
  __shared__ float wpar[8];
  if (lane == 0) wpar[w] = wacc;
  __syncthreads();
  if (threadIdx.x == 0) {
    float s = 0.0f;
#pragma unroll
    for (int ww = 0; ww < 8; ww++) s += wpar[ww];
    g_resacc[wq][slice][bm] = s;
  }
}

// ---------------------------------------------------------------------------
// final kernel: applies the 9th LM update, then geodesic + argmin + output.
// ---------------------------------------------------------------------------
__global__ void final_kernel(const float* __restrict__ Tpred, float* __restrict__ out,
                             float damping_last)
{
  int b = blockIdx.x;
  int m = threadIdx.x;
  __shared__ float tot[M_HYP];
  if (m < M_HYP) {
    float Tc[16];
    const float* Tsrc = g_Tbuf[0] + (size_t)(b * M_HYP + m) * 16;
#pragma unroll
    for (int i = 0; i < 16; i++) Tc[i] = Tsrc[i];
    float c = 0.0f;
    if (m < M16) {
      int bm = b * M16 + m;
      float rs = 0.0f;
#pragma unroll
      for (int p = 0; p < PS; p++) rs += g_resacc[0][p][bm];
      c = rs * (1.0f / N_PTS);
      apply_update(Tc, bm, 8, damping_last, c);
    }
    const float* P = Tpred + b * 16;
    float Ri[9] = { P[0], P[4], P[8],  P[1], P[5], P[9],  P[2], P[6], P[10] };
    float tix = -(Ri[0] * P[3] + Ri[1] * P[7] + Ri[2] * P[11]);
    float tiy = -(Ri[3] * P[3] + Ri[4] * P[7] + Ri[5] * P[11]);
    float tiz = -(Ri[6] * P[3] + Ri[7] * P[7] + Ri[8] * P[11]);
    float Ti[16] = { Ri[0], Ri[1], Ri[2], tix,
                     Ri[3], Ri[4], Ri[5], tiy,
                     Ri[6], Ri[7], Ri[8], tiz,
                     0.f, 0.f, 0.f, 1.f };
    float A[16];
#pragma unroll
    for (int i = 0; i < 4; i++)
#pragma unroll
      for (int j = 0; j < 4; j++)
        A[i * 4 + j] = Tc[i * 4 + 0] * Ti[0 * 4 + j] + Tc[i * 4 + 1] * Ti[1 * 4 + j]
                     + Tc[i * 4 + 2] * Ti[2 * 4 + j] + Tc[i * 4 + 3] * Ti[3 * 4 + j];
    float cos_a = (A[0] + A[5] + A[10] - 1.0f) * 0.5f;
    const float CL = (float)(1.0 - 1e-7);
    cos_a = fminf(fmaxf(cos_a, -CL), CL);
    float theta = acosf(cos_a);
    float th = fmaxf(theta, 1e-8f);
    float sn = fmaxf(sinf(th), 1e-8f);
    float wx = (A[9] - A[6]) / (2.0f * sn) * th;
    float wy = (A[2] - A[8]) / (2.0f * sn) * th;
    float wz = (A[4] - A[1]) / (2.0f * sn) * th;
    if (fabsf(theta) < 1e-6f) { wx = 0.f; wy = 0.f; wz = 0.f; }
    float tx = A[3], ty = A[7], tz = A[11];
    float geod = sqrtf(tx * tx + ty * ty + tz * tz + wx * wx + wy * wy + wz * wz);
    tot[m] = c + geod;
    out[128 + b * M_HYP + m] = c;
    float* Tdst = g_Tbuf[1] + (size_t)(b * M_HYP + m) * 16;
#pragma unroll
    for (int i = 0; i < 16; i++) Tdst[i] = Tc[i];
  }
  __syncthreads();
  if (m == 0) {
    int best = 0;
    float bv = tot[0];
    for (int i = 1; i < M_HYP; i++)
      if (tot[i] < bv) { bv = tot[i]; best = i; }
    const float* Tb = g_Tbuf[1] + (size_t)(b * M_HYP + best) * 16;
#pragma unroll
    for (int i = 0; i < 16; i++) out[b * 16 + i] = Tb[i];
  }
}

// ---------------------------------------------------------------------------
// Host launch
// ---------------------------------------------------------------------------
extern "C" void kernel_launch(void* const* d_in, const int* in_sizes, int n_in,
                              void* d_out, int out_size)
{
  const float* T_pred = (const float*)d_in[0];
  const float* geo    = (const float*)d_in[1];
  const float* Kin    = (const float*)d_in[2];
  const float* q0 = (const float*)d_in[3];
  const float* q1 = (const float*)d_in[4];
  const float* q2 = (const float*)d_in[5];
  const float* r0 = (const float*)d_in[6];
  const float* r1 = (const float*)d_in[7];
  const float* r2 = (const float*)d_in[8];
  const float* u0 = (const float*)d_in[9];
  const float* u1 = (const float*)d_in[10];
  const float* u2 = (const float*)d_in[11];
  float* out = (float*)d_out;

  __nv_bfloat16 *D0p, *D1p, *D2p;
  cudaGetSymbolAddress((void**)&D0p, g_D0);
  cudaGetSymbolAddress((void**)&D1p, g_D1);
  cudaGetSymbolAddress((void**)&D2p, g_D2);

  // side stream (LOW priority) + events, created once on the uncaptured call
  static cudaStream_t s2 = nullptr;
  static cudaEvent_t evFork = nullptr, evJoin = nullptr;
  static bool tried = false;
  if (!tried) {
    tried = true;
    int loPri = 0, hiPri = 0;
    cudaDeviceGetStreamPriorityRange(&loPri, &hiPri);
    if (cudaStreamCreateWithPriority(&s2, cudaStreamNonBlocking, loPri) != cudaSuccess)
      s2 = nullptr;
    if (cudaEventCreateWithFlags(&evFork, cudaEventDisableTiming) != cudaSuccess) evFork = nullptr;
    if (cudaEventCreateWithFlags(&evJoin, cudaEventDisableTiming) != cudaSuccess) evJoin = nullptr;
  }
  bool use2 = (s2 && evFork && evJoin);

  unsigned hk0, hk1;
  threefry2x32(0u, 42u, 0u, 0u, &hk0, &hk1);

  // prep A (hyp + noise + L0) first on main stream — gates iteration 0.
  // prep B (L1+L2) forked onto the low-priority side stream.
  if (use2) {
    cudaEventRecord(evFork, 0);
    prep_kernel_A<<<B_SZ + 1 + T0_TILES, 256>>>(q0, r0, D0p, T_pred, hk0, hk1);
    cudaStreamWaitEvent(s2, evFork, 0);
    prep_kernel_B<<<T1_TILES + T2_TILES, 256, 0, s2>>>(q1, r1, q2, r2, D1p, D2p);
    cudaEventRecord(evJoin, s2);
  } else {
    prep_kernel_A<<<B_SZ + 1 + T0_TILES, 256>>>(q0, r0, D0p, T_pred, hk0, hk1);
    prep_kernel_B<<<T1_TILES + T2_TILES, 256>>>(q1, r1, q2, r2, D1p, D2p);
  }

  const int   lvl[N_ITER]  = {0, 0, 1, 1, 1, 2, 2, 2, 2};
  const float damp[3]      = {0.001f, 0.0005f, 0.00025f};
  const int   grid_res = B_SZ * M16 * PS;    // 1024 blocks
  for (int k = 0; k < N_ITER; k++) {
    int level = lvl[k];
    if (k == 2 && use2) cudaStreamWaitEvent(0, evJoin, 0);   // join before L1 use
    float scale = 1.0f / (4.0f / (float)(1 << level));
    float dprev = (k > 0) ? damp[lvl[k - 1]] : 0.0f;
    if (level == 0)
      residual_kernel<4><<<grid_res, 256>>>(D0p, u0, geo, Kin, C0, H0, W0, scale, k, dprev);
    else if (level == 1)
      residual_kernel<2><<<grid_res, 256>>>(D1p, u1, geo, Kin, C1, H1, W1, scale, k, dprev);
    else
      residual_kernel<1><<<grid_res, 256>>>(D2p, u2, geo, Kin, C2, H2, W2, scale, k, dprev);
  }

  final_kernel<<<B_SZ, M_HYP>>>(T_pred, out, damp[2]);
  (void)in_sizes; (void)n_in; (void)out_size;
}

// round 17
// speedup vs baseline: 1.2166x; 1.0399x over previous
#include <cuda_runtime.h>
#include <cuda_bf16.h>
#include <math.h>

// ---------------------------------------------------------------------------
// Problem dimensions (fixed by the reference setup)
// ---------------------------------------------------------------------------
#define B_SZ   8
#define N_PTS  500
#define M_HYP  144
#define M16    16
#define PS     8           // point slices per (b,m): 63 points each (last: 59)
#define N_ITER 9

#define C0 128
#define H0 48
#define W0 64
#define C1 64
#define H1 96
#define W1 128
#define C2 32
#define H2 192
#define W2 256

// transpose tile counts (32x32 tiles)
#define T0_TILES ((H0*W0/32) * (C0/32) * B_SZ)   // 3072
#define T1_TILES ((H1*W1/32) * (C1/32) * B_SZ)   // 6144
#define T2_TILES ((H2*W2/32) * (C2/32) * B_SZ)   // 12288

// ---------------------------------------------------------------------------
// Scratch (__device__ globals — no allocation allowed). D stored as bf16.
// ---------------------------------------------------------------------------
__device__ __nv_bfloat16 g_D0[(size_t)B_SZ * H0 * W0 * C0];   // q0-r0, channel-last
__device__ __nv_bfloat16 g_D1[(size_t)B_SZ * H1 * W1 * C1];
__device__ __nv_bfloat16 g_D2[(size_t)B_SZ * H2 * W2 * C2];
__device__ float g_Tbuf[2][B_SZ * M_HYP * 16];       // double-buffered poses
__device__ float g_resacc[2][PS][B_SZ * M16];         // double-buffered partial residuals
__device__ float g_noise[N_ITER * B_SZ * M16 * 6];    // precomputed LM noise (m<16 only)

// ---------------------------------------------------------------------------
// Threefry-2x32 (exactly JAX's 20-round schedule; KAT-verified)
// ---------------------------------------------------------------------------
__host__ __device__ __forceinline__ void threefry2x32(
    unsigned k0, unsigned k1, unsigned x0, unsigned x1,
    unsigned* o0, unsigned* o1)
{
  unsigned ks2 = k0 ^ k1 ^ 0x1BD11BDAu;
#define TFR(r) { x0 += x1; x1 = (x1 << (r)) | (x1 >> (32 - (r))); x1 ^= x0; }
  x0 += k0;  x1 += k1;
  TFR(13) TFR(15) TFR(26) TFR(6)
  x0 += k1;  x1 += ks2 + 1u;
  TFR(17) TFR(29) TFR(16) TFR(24)
  x0 += ks2; x1 += k0 + 2u;
  TFR(13) TFR(15) TFR(26) TFR(6)
  x0 += k0;  x1 += k1 + 3u;
  TFR(17) TFR(29) TFR(16) TFR(24)
  x0 += k1;  x1 += ks2 + 4u;
  TFR(13) TFR(15) TFR(26) TFR(6)
  x0 += ks2; x1 += k0 + 5u;
#undef TFR
  *o0 = x0; *o1 = x1;
}

// Giles/XLA erfinv (same coefficients as XLA ErfInv32)
__device__ __forceinline__ float erfinv_f(float x)
{
  float w = -log1pf(-x * x);
  float p;
  if (w < 5.0f) {
    w = w - 2.5f;
    p = 2.81022636e-08f;
    p = fmaf(p, w, 3.43273939e-07f);
    p = fmaf(p, w, -3.5233877e-06f);
    p = fmaf(p, w, -4.39150654e-06f);
    p = fmaf(p, w, 0.00021858087f);
    p = fmaf(p, w, -0.00125372503f);
    p = fmaf(p, w, -0.00417768164f);
    p = fmaf(p, w, 0.246640727f);
    p = fmaf(p, w, 1.50140941f);
  } else {
    w = sqrtf(w) - 3.0f;
    p = -0.000200214257f;
    p = fmaf(p, w, 0.000100950558f);
    p = fmaf(p, w, 0.00134934322f);
    p = fmaf(p, w, -0.00367342844f);
    p = fmaf(p, w, 0.00573950773f);
    p = fmaf(p, w, -0.0076224613f);
    p = fmaf(p, w, 0.00943887047f);
    p = fmaf(p, w, 1.00167406f);
    p = fmaf(p, w, 2.83297682f);
  }
  return p * x;
}

__device__ __forceinline__ float bits_to_normal(unsigned bits)
{
  float u = __uint_as_float((bits >> 9) | 0x3f800000u) - 1.0f;
  const float lo = -0.99999994f;
  float v = fmaxf(lo, u * 2.0f + lo);
  return 1.41421356237f * erfinv_f(v);
}

// PARTITIONABLE threefry: (y0,y1) = threefry(key; 0, j); 32-bit draw = y0 ^ y1.
__device__ __forceinline__ float jax_normal_elem(unsigned k0, unsigned k1, unsigned j)
{
  unsigned y0, y1;
  threefry2x32(k0, k1, 0u, j, &y0, &y1);
  return bits_to_normal(y0 ^ y1);
}

// ---------------------------------------------------------------------------
// se3_exp (matches reference element-by-element)
// ---------------------------------------------------------------------------
__device__ __forceinline__ void mat3mul(const float* A, const float* Bm, float* Cm)
{
#pragma unroll
  for (int i = 0; i < 3; i++)
#pragma unroll
    for (int j = 0; j < 3; j++)
      Cm[i * 3 + j] = A[i * 3 + 0] * Bm[0 * 3 + j] + A[i * 3 + 1] * Bm[1 * 3 + j] + A[i * 3 + 2] * Bm[2 * 3 + j];
}

__device__ void se3_exp6(const float xi[6], float T[16])
{
  float tx = xi[0], ty = xi[1], tz = xi[2];
  float wx = xi[3], wy = xi[4], wz = xi[5];
  float theta = fmaxf(sqrtf(wx * wx + wy * wy + wz * wz), 1e-8f);
  float kx = wx / theta, ky = wy / theta, kz = wz / theta;
  float K[9] = { 0.f, -kz, ky,  kz, 0.f, -kx,  -ky, kx, 0.f };
  float KK[9];
  mat3mul(K, K, KK);
  float st = sinf(theta);
  float ct = 1.0f - cosf(theta);
  float a  = ct / theta;
  float bb = 1.0f - st / theta;
  float R[9], V[9];
#pragma unroll
  for (int i = 0; i < 9; i++) {
    float e = (i == 0 || i == 4 || i == 8) ? 1.0f : 0.0f;
    R[i] = e + st * K[i] + ct * KK[i];
    V[i] = e + a  * K[i] + bb * KK[i];
  }
  float tox = V[0] * tx + V[1] * ty + V[2] * tz;
  float toy = V[3] * tx + V[4] * ty + V[5] * tz;
  float toz = V[6] * tx + V[7] * ty + V[8] * tz;
  T[0] = R[0]; T[1] = R[1]; T[2]  = R[2]; T[3]  = tox;
  T[4] = R[3]; T[5] = R[4]; T[6]  = R[5]; T[7]  = toy;
  T[8] = R[6]; T[9] = R[7]; T[10] = R[8]; T[11] = toz;
  T[12] = 0.f; T[13] = 0.f; T[14] = 0.f; T[15] = 1.f;
}

// Apply LM delta for item bm (= b*16+m): T_out = se3_exp(step) @ T_in
__device__ __forceinline__ void apply_update(
    float Tm[16], int bm, int noise_iter, float damping, float res)
{
  const float* nz = g_noise + ((size_t)(noise_iter * (B_SZ * M16) + bm)) * 6;
  float s1 = -damping * res * 0.01f;
  float xi[6];
#pragma unroll
  for (int k = 0; k < 6; k++) xi[k] = s1 * nz[k];
  float D[16];
  se3_exp6(xi, D);
  float Told[16];
#pragma unroll
  for (int t = 0; t < 16; t++) Told[t] = Tm[t];
#pragma unroll
  for (int r = 0; r < 4; r++)
#pragma unroll
    for (int cc = 0; cc < 4; cc++)
      Tm[r * 4 + cc] = D[r * 4 + 0] * Told[0 * 4 + cc] + D[r * 4 + 1] * Told[1 * 4 + cc]
                     + D[r * 4 + 2] * Told[2 * 4 + cc] + D[r * 4 + 3] * Told[3 * 4 + cc];
}

// ---------------------------------------------------------------------------
// Transpose helper: one 32x32 tile of D = q - r, (B,C,HW) -> (B,HW,C), bf16
// ---------------------------------------------------------------------------
__device__ __forceinline__ void do_tile(
    const float* __restrict__ q, const float* __restrict__ r,
    __nv_bfloat16* __restrict__ Dt, int C, int HW,
    int b, int c0, int hw0, float* tile /* [32][33] */)
{
  const float* qb = q + (size_t)b * C * HW;
  const float* rb = r + (size_t)b * C * HW;
  __nv_bfloat16* Db = Dt + (size_t)b * HW * C;
  int tx = threadIdx.x & 31, ty = threadIdx.x >> 5;
#pragma unroll
  for (int i = ty; i < 32; i += 8) {
    int c = c0 + i, hw = hw0 + tx;
    tile[i * 33 + tx] = qb[(size_t)c * HW + hw] - rb[(size_t)c * HW + hw];
  }
  __syncthreads();
  int tid = threadIdx.x;
#pragma unroll
  for (int idx = tid; idx < 32 * 16; idx += 256) {
    int row = idx >> 4;
    int pr  = idx & 15;
    __nv_bfloat162 h = __floats2bfloat162_rn(tile[(2 * pr) * 33 + row],
                                             tile[(2 * pr + 1) * 33 + row]);
    *(__nv_bfloat162*)(Db + (size_t)(hw0 + row) * C + c0 + 2 * pr) = h;
  }
}

// ---------------------------------------------------------------------------
// prep A: blocks [0,8) = hypotheses; block 8 = noise; rest = L0 tiles
// ---------------------------------------------------------------------------
__global__ __launch_bounds__(256) void prep_kernel_A(
    const float* __restrict__ q0, const float* __restrict__ r0,
    __nv_bfloat16* __restrict__ D0,
    const float* __restrict__ Tpred, unsigned k0, unsigned k1)
{
  __shared__ float tile[32 * 33];
  int blk = blockIdx.x;
  if (blk < B_SZ) {
    int m = threadIdx.x;
    int b = blk;
    if (m >= M_HYP) return;
    float xi[6];
#pragma unroll
    for (int k = 0; k < 3; k++)
      xi[k] = jax_normal_elem(k0, k1, (unsigned)(m * 3 + k));
    int pi = m / 12, yj = m % 12;
    const float D2R = (float)(3.14159265358979323846 / 180.0);
    xi[3] = 0.0f;
    xi[4] = (-11.0f + 2.0f * (float)pi) * D2R;
    xi[5] = (-11.0f + 2.0f * (float)yj) * D2R;
    float dT[16];
    se3_exp6(xi, dT);
    const float* P = Tpred + b * 16;
    size_t off = (size_t)(b * M_HYP + m) * 16;
#pragma unroll
    for (int i = 0; i < 4; i++)
#pragma unroll
      for (int j = 0; j < 4; j++) {
        float v = dT[i * 4 + 0] * P[0 * 4 + j] + dT[i * 4 + 1] * P[1 * 4 + j]
                + dT[i * 4 + 2] * P[2 * 4 + j] + dT[i * 4 + 3] * P[3 * 4 + j];
        g_Tbuf[0][off + i * 4 + j] = v;
        g_Tbuf[1][off + i * 4 + j] = v;
      }
    return;
  }
  blk -= B_SZ;
  if (blk == 0) {
    const int LI[N_ITER] = {100, 101, 110, 111, 112, 120, 121, 122, 123};
    int tid = threadIdx.x;
    for (int it = 0; it < N_ITER; it++) {
      unsigned ik0, ik1;
      threefry2x32(0u, 42u, 0u, (unsigned)LI[it], &ik0, &ik1);
      for (int idx = tid; idx < B_SZ * M16 * 6; idx += 256) {
        int i = idx / 6, k = idx % 6;
        int b = i >> 4, m = i & 15;
        unsigned j = (unsigned)((b * M_HYP + m) * 6 + k);
        g_noise[it * (B_SZ * M16 * 6) + idx] = jax_normal_elem(ik0, ik1, j);
      }
    }
    return;
  }
  blk -= 1;
  {
    const int HWT = H0 * W0 / 32, CT = C0 / 32;
    int b = blk / (HWT * CT);
    int rem = blk % (HWT * CT);
    int c0 = (rem / HWT) * 32, hw0 = (rem % HWT) * 32;
    do_tile(q0, r0, D0, C0, H0 * W0, b, c0, hw0, tile);
  }
}

// ---------------------------------------------------------------------------
// prep B: L1 + L2 tiles (overlapped with the two L0 residual iterations)
// ---------------------------------------------------------------------------
__global__ __launch_bounds__(256) void prep_kernel_B(
    const float* __restrict__ q1, const float* __restrict__ r1,
    const float* __restrict__ q2, const float* __restrict__ r2,
    __nv_bfloat16* __restrict__ D1, __nv_bfloat16* __restrict__ D2)
{
  __shared__ float tile[32 * 33];
  int blk = blockIdx.x;
  if (blk < T1_TILES) {
    const int HWT = H1 * W1 / 32, CT = C1 / 32;
    int b = blk / (HWT * CT);
    int rem = blk % (HWT * CT);
    int c0 = (rem / HWT) * 32, hw0 = (rem % HWT) * 32;
    do_tile(q1, r1, D1, C1, H1 * W1, b, c0, hw0, tile);
    return;
  }
  blk -= T1_TILES;
  {
    const int HWT = H2 * W2 / 32;
    int b = blk / HWT;
    int hw0 = (blk % HWT) * 32;
    do_tile(q2, r2, D2, C2, H2 * W2, b, 0, hw0, tile);
  }
}

// ---------------------------------------------------------------------------
// Residual kernel. grid = B*16*PS = 1024 blocks, 256 threads (8 warps).
// LM-update prologue runs in WARP 0 ONLY; Tm broadcast via shared memory.
// Tm-independent loads hoisted above the barrier.
// Warp w owns points n = slice*63 + w + 8*p (p = 0..vc-1, vc <= 8).
// CPL=1 (level 2): TWO points per inner iteration — lanes 0-15 handle point
// p (16 bf162 pairs = 32 ch), lanes 16-31 handle point p+1; per-lane shuffle
// source index selects each half's point. Halves shuffle + loop overhead.
// ---------------------------------------------------------------------------
template <int CPL>
__global__ __launch_bounds__(256) void residual_kernel(
    const __nv_bfloat16* __restrict__ Dt, const float* __restrict__ Umap,
    const float* __restrict__ geo, const float* __restrict__ Kin,
    int C, int H, int W, float scale, int iter, float damping_prev)
{
  int bm    = blockIdx.x >> 3;
  int slice = blockIdx.x & 7;
  int b = bm >> 4, m = bm & 15;
  int lane = threadIdx.x & 31, w = threadIdx.x >> 5;
  int rp = (iter + 1) & 1, wq = iter & 1;

  const __nv_bfloat16* Db = Dt + (size_t)b * H * W * C;
  const float* Ub = Umap + (size_t)b * H * W;
  const float* G  = geo + (size_t)b * N_PTS * 3;

  // ---- Tm-independent loads first (in flight during warp-0 prologue) ----
  int nbeg = slice * 63 + w;
  int nend = min(N_PTS, slice * 63 + 63);
  int vc = (nend - nbeg + 7) >> 3;               // 1..8 points for this warp
  int n = min(nbeg + 8 * (lane & 7), N_PTS - 1);
  float X = __ldg(G + n * 3 + 0);
  float Y = __ldg(G + n * 3 + 1);
  float Z = __ldg(G + n * 3 + 2);
  float fx = __ldg(Kin + b * 9 + 0) * scale, cx = __ldg(Kin + b * 9 + 2) * scale;
  float fy = __ldg(Kin + b * 9 + 4) * scale, cy = __ldg(Kin + b * 9 + 5) * scale;

  // ---- prologue: WARP 0 computes T_iter; broadcast via shared ----
  __shared__ float sT[16];
  if (w == 0) {
    float Tm[16];
    const float* Tsrc = g_Tbuf[rp] + (size_t)(b * M_HYP + m) * 16;
#pragma unroll
    for (int i = 0; i < 16; i++) Tm[i] = Tsrc[i];
    if (iter > 0) {
      float rs = 0.0f;
#pragma unroll
      for (int p = 0; p < PS; p++) rs += g_resacc[rp][p][bm];
      float res = rs * (1.0f / N_PTS);
      apply_update(Tm, bm, iter - 1, damping_prev, res);
      if (slice == 0 && lane < 16)
        g_Tbuf[wq][(size_t)(b * M_HYP + m) * 16 + lane] = Tm[lane];
    }
    if (lane < 16) sT[lane] = Tm[lane];
  }
  __syncthreads();

  float T00 = sT[0], T01 = sT[1], T02 = sT[2],  T03 = sT[3];
  float T10 = sT[4], T11 = sT[5], T12 = sT[6],  T13 = sT[7];
  float T20 = sT[8], T21 = sT[9], T22 = sT[10], T23 = sT[11];

  // ---- projection: lane l projects point slice*63 + w + 8*l ----
  float Wm1 = (float)(W - 1), Hm1 = (float)(H - 1);
  int o00, o01, o10, o11;
  float w00, w01, w10, w11, us;
  {
    float px = T00 * X + T01 * Y + T02 * Z + T03;
    float py = T10 * X + T11 * Y + T12 * Z + T13;
    float pz = T20 * X + T21 * Y + T22 * Z + T23;
    float z  = fmaxf(pz, 1e-6f);
    float u  = fx * (px / z) + cx;
    float v  = fy * (py / z) + cy;
    float gx = 2.0f * u / Wm1 - 1.0f;
    float gy = 2.0f * v / Hm1 - 1.0f;
    float xs = fminf(fmaxf(((gx + 1.0f) * (float)W - 1.0f) * 0.5f, 0.0f), Wm1);
    float ys = fminf(fmaxf(((gy + 1.0f) * (float)H - 1.0f) * 0.5f, 0.0f), Hm1);
    float x0f = floorf(xs), y0f = floorf(ys);
    float x1f = fminf(x0f + 1.0f, Wm1), y1f = fminf(y0f + 1.0f, Hm1);
    float wx = xs - x0f, wy = ys - y0f;
    int x0 = (int)x0f, x1 = (int)x1f, y0 = (int)y0f, y1 = (int)y1f;
    w00 = (1.0f - wx) * (1.0f - wy); w01 = wx * (1.0f - wy);
    w10 = (1.0f - wx) * wy;          w11 = wx * wy;
    int r0 = y0 * W, r1 = y1 * W;
    us = w00 * __ldg(Ub + r0 + x0) + w01 * __ldg(Ub + r0 + x1)
       + w10 * __ldg(Ub + r1 + x0) + w11 * __ldg(Ub + r1 + x1);
    o00 = (r0 + x0) * 32; o01 = (r0 + x1) * 32;
    o10 = (r1 + x0) * 32; o11 = (r1 + x1) * 32;
  }

  float wacc = 0.0f;

  if constexpr (CPL == 4) {
    const uint2* base = (const uint2*)Db;
    uint2 ca, cb, cc2, cd;
    float cw00, cw01, cw10, cw11, cus;
    {
      int a00 = __shfl_sync(0xffffffffu, o00, 0), a01 = __shfl_sync(0xffffffffu, o01, 0);
      int a10 = __shfl_sync(0xffffffffu, o10, 0), a11 = __shfl_sync(0xffffffffu, o11, 0);
      cw00 = __shfl_sync(0xffffffffu, w00, 0); cw01 = __shfl_sync(0xffffffffu, w01, 0);
      cw10 = __shfl_sync(0xffffffffu, w10, 0); cw11 = __shfl_sync(0xffffffffu, w11, 0);
      cus  = __shfl_sync(0xffffffffu, us,  0);
      ca = __ldg(base + a00 + lane); cb = __ldg(base + a01 + lane);
      cc2 = __ldg(base + a10 + lane); cd = __ldg(base + a11 + lane);
    }
    for (int p = 0; p < vc; p++) {
      uint2 na = {}, nb = {}, nc = {}, nd = {};
      float nw00 = 0, nw01 = 0, nw10 = 0, nw11 = 0, nus = 0;
      if (p + 1 < vc) {
        int a00 = __shfl_sync(0xffffffffu, o00, p + 1), a01 = __shfl_sync(0xffffffffu, o01, p + 1);
        int a10 = __shfl_sync(0xffffffffu, o10, p + 1), a11 = __shfl_sync(0xffffffffu, o11, p + 1);
        nw00 = __shfl_sync(0xffffffffu, w00, p + 1); nw01 = __shfl_sync(0xffffffffu, w01, p + 1);
        nw10 = __shfl_sync(0xffffffffu, w10, p + 1); nw11 = __shfl_sync(0xffffffffu, w11, p + 1);
        nus  = __shfl_sync(0xffffffffu, us,  p + 1);
        na = __ldg(base + a00 + lane); nb = __ldg(base + a01 + lane);
        nc = __ldg(base + a10 + lane); nd = __ldg(base + a11 + lane);
      }
      float2 a0 = __bfloat1622float2(*(__nv_bfloat162*)&ca.x);
      float2 a1 = __bfloat1622float2(*(__nv_bfloat162*)&ca.y);
      float2 b0 = __bfloat1622float2(*(__nv_bfloat162*)&cb.x);
      float2 b1 = __bfloat1622float2(*(__nv_bfloat162*)&cb.y);
      float2 c0v = __bfloat1622float2(*(__nv_bfloat162*)&cc2.x);
      float2 c1 = __bfloat1622float2(*(__nv_bfloat162*)&cc2.y);
      float2 d0v = __bfloat1622float2(*(__nv_bfloat162*)&cd.x);
      float2 d1 = __bfloat1622float2(*(__nv_bfloat162*)&cd.y);
      float e0 = cw00 * a0.x; e0 = fmaf(cw01, b0.x, e0); e0 = fmaf(cw10, c0v.x, e0); e0 = fmaf(cw11, d0v.x, e0);
      float e1 = cw00 * a0.y; e1 = fmaf(cw01, b0.y, e1); e1 = fmaf(cw10, c0v.y, e1); e1 = fmaf(cw11, d0v.y, e1);
      float e2 = cw00 * a1.x; e2 = fmaf(cw01, b1.x, e2); e2 = fmaf(cw10, c1.x, e2); e2 = fmaf(cw11, d1.x, e2);
      float e3 = cw00 * a1.y; e3 = fmaf(cw01, b1.y, e3); e3 = fmaf(cw10, c1.y, e3); e3 = fmaf(cw11, d1.y, e3);
      float spt = e0 * e0 + e1 * e1 + e2 * e2 + e3 * e3;
      wacc = fmaf(cus, spt, wacc);
      ca = na; cb = nb; cc2 = nc; cd = nd;
      cw00 = nw00; cw01 = nw01; cw10 = nw10; cw11 = nw11; cus = nus;
    }
  } else if constexpr (CPL == 2) {
    const unsigned* base = (const unsigned*)Db;
    unsigned ca, cb, cc2, cd;
    float cw00, cw01, cw10, cw11, cus;
    {
      int a00 = __shfl_sync(0xffffffffu, o00, 0), a01 = __shfl_sync(0xffffffffu, o01, 0);
      int a10 = __shfl_sync(0xffffffffu, o10, 0), a11 = __shfl_sync(0xffffffffu, o11, 0);
      cw00 = __shfl_sync(0xffffffffu, w00, 0); cw01 = __shfl_sync(0xffffffffu, w01, 0);
      cw10 = __shfl_sync(0xffffffffu, w10, 0); cw11 = __shfl_sync(0xffffffffu, w11, 0);
      cus  = __shfl_sync(0xffffffffu, us,  0);
      ca = __ldg(base + a00 + lane); cb = __ldg(base + a01 + lane);
      cc2 = __ldg(base + a10 + lane); cd = __ldg(base + a11 + lane);
    }
    for (int p = 0; p < vc; p++) {
      unsigned na = 0, nb = 0, nc = 0, nd = 0;
      float nw00 = 0, nw01 = 0, nw10 = 0, nw11 = 0, nus = 0;
      if (p + 1 < vc) {
        int a00 = __shfl_sync(0xffffffffu, o00, p + 1), a01 = __shfl_sync(0xffffffffu, o01, p + 1);
        int a10 = __shfl_sync(0xffffffffu, o10, p + 1), a11 = __shfl_sync(0xffffffffu, o11, p + 1);
        nw00 = __shfl_sync(0xffffffffu, w00, p + 1); nw01 = __shfl_sync(0xffffffffu, w01, p + 1);
        nw10 = __shfl_sync(0xffffffffu, w10, p + 1); nw11 = __shfl_sync(0xffffffffu, w11, p + 1);
        nus  = __shfl_sync(0xffffffffu, us,  p + 1);
        na = __ldg(base + a00 + lane); nb = __ldg(base + a01 + lane);
        nc = __ldg(base + a10 + lane); nd = __ldg(base + a11 + lane);
      }
      float2 a = __bfloat1622float2(*(__nv_bfloat162*)&ca);
      float2 bq = __bfloat1622float2(*(__nv_bfloat162*)&cb);
      float2 c = __bfloat1622float2(*(__nv_bfloat162*)&cc2);
      float2 d = __bfloat1622float2(*(__nv_bfloat162*)&cd);
      float e0 = cw00 * a.x; e0 = fmaf(cw01, bq.x, e0); e0 = fmaf(cw10, c.x, e0); e0 = fmaf(cw11, d.x, e0);
      float e1 = cw00 * a.y; e1 = fmaf(cw01, bq.y, e1); e1 = fmaf(cw10, c.y, e1); e1 = fmaf(cw11, d.y, e1);
      float spt = e0 * e0 + e1 * e1;
      wacc = fmaf(cus, spt, wacc);
      ca = na; cb = nb; cc2 = nc; cd = nd;
      cw00 = nw00; cw01 = nw01; cw10 = nw10; cw11 = nw11; cus = nus;
    }
  } else {
    // CPL == 1: two points per iteration. half = lane>>4 picks point p+half;
    // ch = lane&15 covers bf162 pair (channels 2ch, 2ch+1). Address in bf162
    // units = (pixel index)*16 = o/2. Phantom point (sp >= vc) gets us=0.
    const unsigned* base = (const unsigned*)Db;   // bf162 units
    int half = lane >> 4;
    int ch   = lane & 15;
    unsigned ca, cb, cc2, cd;
    float cw00, cw01, cw10, cw11, cus;
    {
      int sp = half;
      int spc = min(sp, vc - 1);
      int a00 = __shfl_sync(0xffffffffu, o00, spc) >> 1;
      int a01 = __shfl_sync(0xffffffffu, o01, spc) >> 1;
      int a10 = __shfl_sync(0xffffffffu, o10, spc) >> 1;
      int a11 = __shfl_sync(0xffffffffu, o11, spc) >> 1;
      cw00 = __shfl_sync(0xffffffffu, w00, spc); cw01 = __shfl_sync(0xffffffffu, w01, spc);
      cw10 = __shfl_sync(0xffffffffu, w10, spc); cw11 = __shfl_sync(0xffffffffu, w11, spc);
      float tus = __shfl_sync(0xffffffffu, us, spc);
      cus = (sp < vc) ? tus : 0.0f;
      ca = __ldg(base + a00 + ch); cb = __ldg(base + a01 + ch);
      cc2 = __ldg(base + a10 + ch); cd = __ldg(base + a11 + ch);
    }
    for (int p = 0; p < vc; p += 2) {
      unsigned na = 0, nb = 0, nc = 0, nd = 0;
      float nw00 = 0, nw01 = 0, nw10 = 0, nw11 = 0, nus = 0;
      if (p + 2 < vc) {
        int sp = p + 2 + half;
        int spc = min(sp, vc - 1);
        int a00 = __shfl_sync(0xffffffffu, o00, spc) >> 1;
        int a01 = __shfl_sync(0xffffffffu, o01, spc) >> 1;
        int a10 = __shfl_sync(0xffffffffu, o10, spc) >> 1;
        int a11 = __shfl_sync(0xffffffffu, o11, spc) >> 1;
        nw00 = __shfl_sync(0xffffffffu, w00, spc); nw01 = __shfl_sync(0xffffffffu, w01, spc);
        nw10 = __shfl_sync(0xffffffffu, w10, spc); nw11 = __shfl_sync(0xffffffffu, w11, spc);
        float tus = __shfl_sync(0xffffffffu, us, spc);
        nus = (sp < vc) ? tus : 0.0f;
        na = __ldg(base + a00 + ch); nb = __ldg(base + a01 + ch);
        nc = __ldg(base + a10 + ch); nd = __ldg(base + a11 + ch);
      }
      float2 a = __bfloat1622float2(*(__nv_bfloat162*)&ca);
      float2 bq = __bfloat1622float2(*(__nv_bfloat162*)&cb);
      float2 c = __bfloat1622float2(*(__nv_bfloat162*)&cc2);
      float2 d = __bfloat1622float2(*(__nv_bfloat162*)&cd);
      float e0 = cw00 * a.x; e0 = fmaf(cw01, bq.x, e0); e0 = fmaf(cw10, c.x, e0); e0 = fmaf(cw11, d.x, e0);
      float e1 = cw00 * a.y; e1 = fmaf(cw01, bq.y, e1); e1 = fmaf(cw10, c.y, e1); e1 = fmaf(cw11, d.y, e1);
      float spt = e0 * e0 + e1 * e1;
      wacc = fmaf(cus, spt, wacc);
      ca = na; cb = nb; cc2 = nc; cd = nd;
      cw00 = nw00; cw01 = nw01; cw10 = nw10; cw11 = nw11; cus = nus;
    }
  }

#pragma unroll
  for (int o = 16; o; o >>= 1) wacc += __shfl_xor_sync(0xffffffffu, wacc, o);
  __shared__ float wpar[8];
  if (lane == 0) wpar[w] = wacc;
  __syncthreads();
  if (threadIdx.x == 0) {
    float s = 0.0f;
#pragma unroll
    for (int ww = 0; ww < 8; ww++) s += wpar[ww];
    g_resacc[wq][slice][bm] = s;
  }
}

// ---------------------------------------------------------------------------
// final kernel: applies the 9th LM update, then geodesic + argmin + output.
// ---------------------------------------------------------------------------
__global__ void final_kernel(const float* __restrict__ Tpred, float* __restrict__ out,
                             float damping_last)
{
  int b = blockIdx.x;
  int m = threadIdx.x;
  __shared__ float tot[M_HYP];
  if (m < M_HYP) {
    float Tc[16];
    const float* Tsrc = g_Tbuf[0] + (size_t)(b * M_HYP + m) * 16;
#pragma unroll
    for (int i = 0; i < 16; i++) Tc[i] = Tsrc[i];
    float c = 0.0f;
    if (m < M16) {
      int bm = b * M16 + m;
      float rs = 0.0f;
#pragma unroll
      for (int p = 0; p < PS; p++) rs += g_resacc[0][p][bm];
      c = rs * (1.0f / N_PTS);
      apply_update(Tc, bm, 8, damping_last, c);
    }
    const float* P = Tpred + b * 16;
    float Ri[9] = { P[0], P[4], P[8],  P[1], P[5], P[9],  P[2], P[6], P[10] };
    float tix = -(Ri[0] * P[3] + Ri[1] * P[7] + Ri[2] * P[11]);
    float tiy = -(Ri[3] * P[3] + Ri[4] * P[7] + Ri[5] * P[11]);
    float tiz = -(Ri[6] * P[3] + Ri[7] * P[7] + Ri[8] * P[11]);
    float Ti[16] = { Ri[0], Ri[1], Ri[2], tix,
                     Ri[3], Ri[4], Ri[5], tiy,
                     Ri[6], Ri[7], Ri[8], tiz,
                     0.f, 0.f, 0.f, 1.f };
    float A[16];
#pragma unroll
    for (int i = 0; i < 4; i++)
#pragma unroll
      for (int j = 0; j < 4; j++)
        A[i * 4 + j] = Tc[i * 4 + 0] * Ti[0 * 4 + j] + Tc[i * 4 + 1] * Ti[1 * 4 + j]
                     + Tc[i * 4 + 2] * Ti[2 * 4 + j] + Tc[i * 4 + 3] * Ti[3 * 4 + j];
    float cos_a = (A[0] + A[5] + A[10] - 1.0f) * 0.5f;
    const float CL = (float)(1.0 - 1e-7);
    cos_a = fminf(fmaxf(cos_a, -CL), CL);
    float theta = acosf(cos_a);
    float th = fmaxf(theta, 1e-8f);
    float sn = fmaxf(sinf(th), 1e-8f);
    float wx = (A[9] - A[6]) / (2.0f * sn) * th;
    float wy = (A[2] - A[8]) / (2.0f * sn) * th;
    float wz = (A[4] - A[1]) / (2.0f * sn) * th;
    if (fabsf(theta) < 1e-6f) { wx = 0.f; wy = 0.f; wz = 0.f; }
    float tx = A[3], ty = A[7], tz = A[11];
    float geod = sqrtf(tx * tx + ty * ty + tz * tz + wx * wx + wy * wy + wz * wz);
    tot[m] = c + geod;
    out[128 + b * M_HYP + m] = c;
    float* Tdst = g_Tbuf[1] + (size_t)(b * M_HYP + m) * 16;
#pragma unroll
    for (int i = 0; i < 16; i++) Tdst[i] = Tc[i];
  }
  __syncthreads();
  if (m == 0) {
    int best = 0;
    float bv = tot[0];
    for (int i = 1; i < M_HYP; i++)
      if (tot[i] < bv) { bv = tot[i]; best = i; }
    const float* Tb = g_Tbuf[1] + (size_t)(b * M_HYP + best) * 16;
#pragma unroll
    for (int i = 0; i < 16; i++) out[b * 16 + i] = Tb[i];
  }
}

// ---------------------------------------------------------------------------
// Host launch
// ---------------------------------------------------------------------------
extern "C" void kernel_launch(void* const* d_in, const int* in_sizes, int n_in,
                              void* d_out, int out_size)
{
  const float* T_pred = (const float*)d_in[0];
  const float* geo    = (const float*)d_in[1];
  const float* Kin    = (const float*)d_in[2];
  const float* q0 = (const float*)d_in[3];
  const float* q1 = (const float*)d_in[4];
  const float* q2 = (const float*)d_in[5];
  const float* r0 = (const float*)d_in[6];
  const float* r1 = (const float*)d_in[7];
  const float* r2 = (const float*)d_in[8];
  const float* u0 = (const float*)d_in[9];
  const float* u1 = (const float*)d_in[10];
  const float* u2 = (const float*)d_in[11];
  float* out = (float*)d_out;

  __nv_bfloat16 *D0p, *D1p, *D2p;
  cudaGetSymbolAddress((void**)&D0p, g_D0);
  cudaGetSymbolAddress((void**)&D1p, g_D1);
  cudaGetSymbolAddress((void**)&D2p, g_D2);

  // side stream (LOW priority) + events, created once on the uncaptured call
  static cudaStream_t s2 = nullptr;
  static cudaEvent_t evFork = nullptr, evJoin = nullptr;
  static bool tried = false;
  if (!tried) {
    tried = true;
    int loPri = 0, hiPri = 0;
    cudaDeviceGetStreamPriorityRange(&loPri, &hiPri);
    if (cudaStreamCreateWithPriority(&s2, cudaStreamNonBlocking, loPri) != cudaSuccess)
      s2 = nullptr;
    if (cudaEventCreateWithFlags(&evFork, cudaEventDisableTiming) != cudaSuccess) evFork = nullptr;
    if (cudaEventCreateWithFlags(&evJoin, cudaEventDisableTiming) != cudaSuccess) evJoin = nullptr;
  }
  bool use2 = (s2 && evFork && evJoin);

  unsigned hk0, hk1;
  threefry2x32(0u, 42u, 0u, 0u, &hk0, &hk1);

  // prep A (hyp + noise + L0) first on main stream — gates iteration 0.
  // prep B (L1+L2) forked onto the low-priority side stream.
  if (use2) {
    cudaEventRecord(evFork, 0);
    prep_kernel_A<<<B_SZ + 1 + T0_TILES, 256>>>(q0, r0, D0p, T_pred, hk0, hk1);
    cudaStreamWaitEvent(s2, evFork, 0);
    prep_kernel_B<<<T1_TILES + T2_TILES, 256, 0, s2>>>(q1, r1, q2, r2, D1p, D2p);
    cudaEventRecord(evJoin, s2);
  } else {
    prep_kernel_A<<<B_SZ + 1 + T0_TILES, 256>>>(q0, r0, D0p, T_pred, hk0, hk1);
    prep_kernel_B<<<T1_TILES + T2_TILES, 256>>>(q1, r1, q2, r2, D1p, D2p);
  }

  const int   lvl[N_ITER]  = {0, 0, 1, 1, 1, 2, 2, 2, 2};
  const float damp[3]      = {0.001f, 0.0005f, 0.00025f};
  const int   grid_res = B_SZ * M16 * PS;    // 1024 blocks
  for (int k = 0; k < N_ITER; k++) {
    int level = lvl[k];
    if (k == 2 && use2) cudaStreamWaitEvent(0, evJoin, 0);   // join before L1 use
    float scale = 1.0f / (4.0f / (float)(1 << level));
    float dprev = (k > 0) ? damp[lvl[k - 1]] : 0.0f;
    if (level == 0)
      residual_kernel<4><<<grid_res, 256>>>(D0p, u0, geo, Kin, C0, H0, W0, scale, k, dprev);
    else if (level == 1)
      residual_kernel<2><<<grid_res, 256>>>(D1p, u1, geo, Kin, C1, H1, W1, scale, k, dprev);
    else
      residual_kernel<1><<<grid_res, 256>>>(D2p, u2, geo, Kin, C2, H2, W2, scale, k, dprev);
  }

  final_kernel<<<B_SZ, M_HYP>>>(T_pred, out, damp[2]);
  (void)in_sizes; (void)n_in; (void)out_size;
}